// round 1
// baseline (speedup 1.0000x reference)
#include <cuda_runtime.h>
#include <cstddef>

#define S_    2048
#define B_    4
#define INDIM 64
#define H_    1024
#define DFF_  1024
#define OUTD  64
#define L_    3
#define NHEAD 4
#define DH    (H_ / NHEAD)   // 256
#define WIN   4
#define TOK   (S_ * B_)      // 8192
#define EPS   1e-5f

// ---------------- scratch (static device globals; no runtime alloc) ----------
__device__ float g_x[TOK * H_];            // running activations
__device__ float g_qkv[TOK * 3 * H_];      // qkv projection
__device__ float g_ctx[TOK * H_];          // attention context
__device__ float g_tmp[TOK * H_];          // attn_out / ff2 output
__device__ float g_h1[TOK * DFF_];         // ff1 output

// ---------------- generic SGEMM: C[M,N] = A[M,K] @ W[N,K]^T + bias, opt relu --
#define BM 128
#define BN 128
#define BK 16
#define TM 8
#define TN 8

__global__ __launch_bounds__(256, 2)
void sgemm_bias(const float* __restrict__ A, const float* __restrict__ W,
                const float* __restrict__ bias, float* __restrict__ C,
                int M, int N, int K, int relu)
{
    __shared__ float As[BK][BM + 4];
    __shared__ float Bs[BK][BN + 4];

    const int bm  = blockIdx.y * BM;
    const int bn  = blockIdx.x * BN;
    const int tid = threadIdx.x;            // 0..255
    const int tx  = tid & 15;               // 16 cols of threads
    const int ty  = tid >> 4;               // 16 rows of threads

    float acc[TM][TN];
#pragma unroll
    for (int i = 0; i < TM; i++)
#pragma unroll
        for (int j = 0; j < TN; j++) acc[i][j] = 0.0f;

    for (int k0 = 0; k0 < K; k0 += BK) {
        // Load A tile (BM x BK), transposed into As[k][m]. 512 float4, 2/thread.
#pragma unroll
        for (int it = 0; it < 2; it++) {
            int idx = tid + it * 256;
            int row = idx >> 2;             // 0..127
            int c4  = (idx & 3) << 2;       // 0,4,8,12
            float4 v = *(const float4*)(A + (size_t)(bm + row) * K + k0 + c4);
            As[c4 + 0][row] = v.x;
            As[c4 + 1][row] = v.y;
            As[c4 + 2][row] = v.z;
            As[c4 + 3][row] = v.w;
        }
        // Load W tile (BN x BK of W, = B^T tile), transposed into Bs[k][n].
#pragma unroll
        for (int it = 0; it < 2; it++) {
            int idx = tid + it * 256;
            int row = idx >> 2;
            int c4  = (idx & 3) << 2;
            float4 v = make_float4(0.f, 0.f, 0.f, 0.f);
            if (bn + row < N)
                v = *(const float4*)(W + (size_t)(bn + row) * K + k0 + c4);
            Bs[c4 + 0][row] = v.x;
            Bs[c4 + 1][row] = v.y;
            Bs[c4 + 2][row] = v.z;
            Bs[c4 + 3][row] = v.w;
        }
        __syncthreads();

#pragma unroll
        for (int k = 0; k < BK; k++) {
            float a[TM], b[TN];
            float4 t0 = *(const float4*)&As[k][ty * TM];
            float4 t1 = *(const float4*)&As[k][ty * TM + 4];
            a[0]=t0.x; a[1]=t0.y; a[2]=t0.z; a[3]=t0.w;
            a[4]=t1.x; a[5]=t1.y; a[6]=t1.z; a[7]=t1.w;
            float4 u0 = *(const float4*)&Bs[k][tx * TN];
            float4 u1 = *(const float4*)&Bs[k][tx * TN + 4];
            b[0]=u0.x; b[1]=u0.y; b[2]=u0.z; b[3]=u0.w;
            b[4]=u1.x; b[5]=u1.y; b[6]=u1.z; b[7]=u1.w;
#pragma unroll
            for (int i = 0; i < TM; i++)
#pragma unroll
                for (int j = 0; j < TN; j++)
                    acc[i][j] = fmaf(a[i], b[j], acc[i][j]);
        }
        __syncthreads();
    }

    // Epilogue: bias (+ optional relu), float4 stores. N is a multiple of 4.
#pragma unroll
    for (int i = 0; i < TM; i++) {
        int m = bm + ty * TM + i;
#pragma unroll
        for (int j4 = 0; j4 < 2; j4++) {
            int n = bn + tx * TN + j4 * 4;
            if (n < N) {
                float4 bv = *(const float4*)(bias + n);
                float4 o;
                o.x = acc[i][j4 * 4 + 0] + bv.x;
                o.y = acc[i][j4 * 4 + 1] + bv.y;
                o.z = acc[i][j4 * 4 + 2] + bv.z;
                o.w = acc[i][j4 * 4 + 3] + bv.w;
                if (relu) {
                    o.x = fmaxf(o.x, 0.f); o.y = fmaxf(o.y, 0.f);
                    o.z = fmaxf(o.z, 0.f); o.w = fmaxf(o.w, 0.f);
                }
                *(float4*)(C + (size_t)m * N + n) = o;
            }
        }
    }
}

// ---------------- banded attention: warp per (token, head) -------------------
// allowed keys for query s: j in [max(0, s-WIN), s]  (<= 5 keys)
__global__ __launch_bounds__(256)
void attn_kernel(const float* __restrict__ qkv, float* __restrict__ ctx)
{
    int w    = (blockIdx.x * blockDim.x + threadIdx.x) >> 5;
    int lane = threadIdx.x & 31;
    if (w >= TOK * NHEAD) return;
    int t = w >> 2;          // token
    int h = w & 3;           // head
    int s = t / B_;
    int b = t - s * B_;

    const float* qp = qkv + (size_t)t * (3 * H_) + h * DH;
    float ql[8];
#pragma unroll
    for (int i = 0; i < 8; i++) ql[i] = qp[lane + i * 32];

    int lo  = s - WIN; if (lo < 0) lo = 0;
    int cnt = s - lo + 1;

    float sc[WIN + 1];
#pragma unroll
    for (int j = 0; j <= WIN; j++) {
        sc[j] = -1e30f;
        if (j < cnt) {
            int tj = (lo + j) * B_ + b;
            const float* kp = qkv + (size_t)tj * (3 * H_) + H_ + h * DH;
            float p = 0.f;
#pragma unroll
            for (int i = 0; i < 8; i++) p = fmaf(ql[i], kp[lane + i * 32], p);
#pragma unroll
            for (int o = 16; o; o >>= 1) p += __shfl_xor_sync(0xFFFFFFFFu, p, o);
            sc[j] = p * 0.0625f;   // 1/sqrt(256)
        }
    }
    float m = sc[0];
#pragma unroll
    for (int j = 1; j <= WIN; j++) m = fmaxf(m, sc[j]);
    float e[WIN + 1];
    float se = 0.f;
#pragma unroll
    for (int j = 0; j <= WIN; j++) {
        e[j] = (j < cnt) ? __expf(sc[j] - m) : 0.f;
        se += e[j];
    }
    float inv = 1.f / se;

    float cx[8];
#pragma unroll
    for (int i = 0; i < 8; i++) cx[i] = 0.f;
    for (int j = 0; j < cnt; j++) {
        int tj = (lo + j) * B_ + b;
        const float* vp = qkv + (size_t)tj * (3 * H_) + 2 * H_ + h * DH;
        float a = e[j] * inv;
#pragma unroll
        for (int i = 0; i < 8; i++) cx[i] = fmaf(a, vp[lane + i * 32], cx[i]);
    }
    float* cp = ctx + (size_t)t * H_ + h * DH;
#pragma unroll
    for (int i = 0; i < 8; i++) cp[lane + i * 32] = cx[i];
}

// ---------------- fused residual + LayerNorm, in-place on x ------------------
__device__ __forceinline__ float block_sum(float v, float* red)
{
#pragma unroll
    for (int o = 16; o; o >>= 1) v += __shfl_xor_sync(0xFFFFFFFFu, v, o);
    int wid = threadIdx.x >> 5, lane = threadIdx.x & 31;
    if (lane == 0) red[wid] = v;
    __syncthreads();
    if (threadIdx.x < 32) {
        float r = (threadIdx.x < 8) ? red[threadIdx.x] : 0.f;
#pragma unroll
        for (int o = 4; o; o >>= 1) r += __shfl_xor_sync(0xFFFFFFFFu, r, o);
        if (threadIdx.x == 0) red[0] = r;
    }
    __syncthreads();
    float r = red[0];
    __syncthreads();      // red reusable after this
    return r;
}

__global__ __launch_bounds__(256)
void resid_ln_kernel(float* __restrict__ x, const float* __restrict__ delta,
                     const float* __restrict__ scale, const float* __restrict__ bias)
{
    __shared__ float red[8];
    int t   = blockIdx.x;
    int tid = threadIdx.x;                  // 256 threads, 4 elems each
    size_t base = (size_t)t * H_ + tid * 4;

    float4 v = *(const float4*)(x + base);
    float4 d = *(const float4*)(delta + base);
    v.x += d.x; v.y += d.y; v.z += d.z; v.w += d.w;

    float s = v.x + v.y + v.z + v.w;
    float mean = block_sum(s, red) * (1.0f / H_);

    float dx = v.x - mean, dy = v.y - mean, dz = v.z - mean, dw = v.w - mean;
    float sq = dx * dx + dy * dy + dz * dz + dw * dw;
    float var = block_sum(sq, red) * (1.0f / H_);
    float rstd = rsqrtf(var + EPS);

    float4 sc = *(const float4*)(scale + tid * 4);
    float4 bi = *(const float4*)(bias + tid * 4);
    float4 o;
    o.x = dx * rstd * sc.x + bi.x;
    o.y = dy * rstd * sc.y + bi.y;
    o.z = dz * rstd * sc.z + bi.z;
    o.w = dw * rstd * sc.w + bi.w;
    *(float4*)(x + base) = o;
}

// ---------------- host orchestration -----------------------------------------
static inline void run_gemm(const float* A, const float* W, const float* bias,
                            float* C, int M, int N, int K, int relu)
{
    dim3 grid((N + BN - 1) / BN, (M + BM - 1) / BM);
    sgemm_bias<<<grid, 256>>>(A, W, bias, C, M, N, K, relu);
}

extern "C" void kernel_launch(void* const* d_in, const int* in_sizes, int n_in,
                              void* d_out, int out_size)
{
    const float* src   = (const float*)d_in[0];
    const float* Wenc  = (const float*)d_in[1];
    const float* benc  = (const float*)d_in[2];
    const float* Wqkv  = (const float*)d_in[3];
    const float* bqkv  = (const float*)d_in[4];
    const float* Wo    = (const float*)d_in[5];
    const float* bo    = (const float*)d_in[6];
    const float* W1    = (const float*)d_in[7];
    const float* b1    = (const float*)d_in[8];
    const float* W2    = (const float*)d_in[9];
    const float* b2    = (const float*)d_in[10];
    const float* ln1_s = (const float*)d_in[11];
    const float* ln1_b = (const float*)d_in[12];
    const float* ln2_s = (const float*)d_in[13];
    const float* ln2_b = (const float*)d_in[14];
    const float* Wout  = (const float*)d_in[15];
    const float* bout  = (const float*)d_in[16];
    float* out = (float*)d_out;

    float *x, *qkv, *ctx, *tmp, *h1;
    cudaGetSymbolAddress((void**)&x,   g_x);
    cudaGetSymbolAddress((void**)&qkv, g_qkv);
    cudaGetSymbolAddress((void**)&ctx, g_ctx);
    cudaGetSymbolAddress((void**)&tmp, g_tmp);
    cudaGetSymbolAddress((void**)&h1,  g_h1);

    // encoder: x = src @ Wenc^T + benc
    run_gemm(src, Wenc, benc, x, TOK, H_, INDIM, 0);

    for (int l = 0; l < L_; l++) {
        const float* Wqkv_l = Wqkv + (size_t)l * 3 * H_ * H_;
        const float* bqkv_l = bqkv + (size_t)l * 3 * H_;
        const float* Wo_l   = Wo   + (size_t)l * H_ * H_;
        const float* bo_l   = bo   + (size_t)l * H_;
        const float* W1_l   = W1   + (size_t)l * DFF_ * H_;
        const float* b1_l   = b1   + (size_t)l * DFF_;
        const float* W2_l   = W2   + (size_t)l * H_ * DFF_;
        const float* b2_l   = b2   + (size_t)l * H_;

        // qkv = x @ Wqkv^T + bqkv
        run_gemm(x, Wqkv_l, bqkv_l, qkv, TOK, 3 * H_, H_, 0);
        // banded attention
        attn_kernel<<<(TOK * NHEAD) / 8, 256>>>(qkv, ctx);
        // attn_out = ctx @ Wo^T + bo
        run_gemm(ctx, Wo_l, bo_l, tmp, TOK, H_, H_, 0);
        // x = LN(x + attn_out)
        resid_ln_kernel<<<TOK, 256>>>(x, tmp, ln1_s + (size_t)l * H_, ln1_b + (size_t)l * H_);
        // h1 = relu(x @ W1^T + b1)
        run_gemm(x, W1_l, b1_l, h1, TOK, DFF_, H_, 1);
        // ff = h1 @ W2^T + b2
        run_gemm(h1, W2_l, b2_l, tmp, TOK, H_, DFF_, 0);
        // x = LN(x + ff)
        resid_ln_kernel<<<TOK, 256>>>(x, tmp, ln2_s + (size_t)l * H_, ln2_b + (size_t)l * H_);
    }

    // out = x @ Wout^T + bout
    run_gemm(x, Wout, bout, out, TOK, OUTD, H_, 0);
}

// round 4
// speedup vs baseline: 1.1332x; 1.1332x over previous
#include <cuda_runtime.h>
#include <cuda_bf16.h>
#include <cstdint>
#include <cstddef>

#define S_    2048
#define B_    4
#define INDIM 64
#define H_    1024
#define DFF_  1024
#define OUTD  64
#define L_    3
#define NHEAD 4
#define DH    (H_ / NHEAD)   // 256
#define WIN   4
#define TOK   (S_ * B_)      // 8192
#define EPS   1e-5f

// ---------------- scratch ----------------------------------------------------
__device__ float g_x[TOK * H_];
__device__ float g_qkv[TOK * 3 * H_];
__device__ float g_ctx[TOK * H_];
__device__ float g_tmp[TOK * H_];
__device__ float g_h1[TOK * DFF_];

__device__ __forceinline__ uint32_t smem_to_u32(const void* p) {
    uint32_t a;
    asm("{ .reg .u64 t; cvta.to.shared.u64 t, %1; cvt.u32.u64 %0, t; }"
        : "=r"(a) : "l"(p));
    return a;
}

// ================= bf16x3 MMA GEMM ===========================================
// C[M,N] = A[M,K] @ W[N,K]^T + bias, optional relu.
// Requires M%128==0, N%128==0, K%32==0.
#define KCH   32                 // K elements per chunk
#define APAD  40                 // padded bf16 row length (80B: conflict-free)
#define TILEB (128 * APAD * 2)   // 10240 bytes per bf16 tile
// buffer layout: [Ahi][Alo][Bhi][Blo], double buffered
#define MM_SMEM (2 * 4 * TILEB)  // 81920 bytes

__device__ __forceinline__ void ldmx4(uint32_t& r0, uint32_t& r1,
                                      uint32_t& r2, uint32_t& r3, uint32_t a) {
    asm volatile("ldmatrix.sync.aligned.m8n8.x4.shared.b16 {%0,%1,%2,%3}, [%4];"
                 : "=r"(r0), "=r"(r1), "=r"(r2), "=r"(r3) : "r"(a));
}
__device__ __forceinline__ void ldmx2(uint32_t& r0, uint32_t& r1, uint32_t a) {
    asm volatile("ldmatrix.sync.aligned.m8n8.x2.shared.b16 {%0,%1}, [%2];"
                 : "=r"(r0), "=r"(r1) : "r"(a));
}
__device__ __forceinline__ void mma16816(float* d, const uint32_t* a, const uint32_t* b) {
    asm volatile("mma.sync.aligned.m16n8k16.row.col.f32.bf16.bf16.f32 "
                 "{%0,%1,%2,%3}, {%4,%5,%6,%7}, {%8,%9}, {%0,%1,%2,%3};"
                 : "+f"(d[0]), "+f"(d[1]), "+f"(d[2]), "+f"(d[3])
                 : "r"(a[0]), "r"(a[1]), "r"(a[2]), "r"(a[3]), "r"(b[0]), "r"(b[1]));
}

__device__ __forceinline__ uint32_t pack_bf16x2(__nv_bfloat16 a, __nv_bfloat16 b) {
    __nv_bfloat162 t = __halves2bfloat162(a, b);
    return *reinterpret_cast<uint32_t*>(&t);
}

// convert 4 fp32 -> 2 packed hi words + 2 packed lo words
__device__ __forceinline__ void split4(float4 v, uint32_t& h01, uint32_t& h23,
                                       uint32_t& l01, uint32_t& l23) {
    __nv_bfloat16 h0 = __float2bfloat16(v.x), h1 = __float2bfloat16(v.y);
    __nv_bfloat16 h2 = __float2bfloat16(v.z), h3 = __float2bfloat16(v.w);
    float r0 = v.x - __bfloat162float(h0), r1 = v.y - __bfloat162float(h1);
    float r2 = v.z - __bfloat162float(h2), r3 = v.w - __bfloat162float(h3);
    h01 = pack_bf16x2(h0, h1); h23 = pack_bf16x2(h2, h3);
    l01 = pack_bf16x2(__float2bfloat16(r0), __float2bfloat16(r1));
    l23 = pack_bf16x2(__float2bfloat16(r2), __float2bfloat16(r3));
}

__global__ __launch_bounds__(256, 1)
void gemm_mma(const float* __restrict__ A, const float* __restrict__ W,
              const float* __restrict__ bias, float* __restrict__ C,
              int M, int N, int K, int relu)
{
    extern __shared__ char smem[];
    const int tid  = threadIdx.x;
    const int wid  = tid >> 5;
    const int lane = tid & 31;
    const int warp_m = wid >> 2;        // 0..1 -> 64-row block
    const int warp_n = wid & 3;         // 0..3 -> 32-col block

    const int tile_m = blockIdx.y * 128;
    const int tile_n = blockIdx.x * 128;
    const int NC = K / KCH;

    // load-phase indexing: 1024 float4 slots per operand, 4 per thread
    const int lr  = tid >> 3;           // row 0..31 step: +32 per i? no: idx below
    (void)lr;

    float acc[4][4][4];
#pragma unroll
    for (int i = 0; i < 4; i++)
#pragma unroll
        for (int j = 0; j < 4; j++)
#pragma unroll
            for (int k = 0; k < 4; k++) acc[i][j][k] = 0.f;

    char* bufc[2] = { smem, smem + 4 * TILEB };

    // ---- helper lambdas -----------------------------------------------------
    auto ldg_chunk = [&](int c, float4* pa, float4* pb) {
        int col0 = c * KCH;
#pragma unroll
        for (int i = 0; i < 4; i++) {
            int idx = tid + i * 256;            // 0..1023
            int r   = idx >> 3;                 // 0..127
            int c4  = (idx & 7) << 2;           // 0..28
            pa[i] = *(const float4*)(A + (size_t)(tile_m + r) * K + col0 + c4);
            pb[i] = *(const float4*)(W + (size_t)(tile_n + r) * K + col0 + c4);
        }
    };
    auto sts_chunk = [&](char* buf, const float4* pa, const float4* pb) {
        char* sAh = buf;
        char* sAl = buf + TILEB;
        char* sBh = buf + 2 * TILEB;
        char* sBl = buf + 3 * TILEB;
#pragma unroll
        for (int i = 0; i < 4; i++) {
            int idx = tid + i * 256;
            int r   = idx >> 3;
            int c4  = (idx & 7) << 2;
            uint32_t off = (uint32_t)(r * APAD + c4) * 2;
            uint32_t h01, h23, l01, l23;
            split4(pa[i], h01, h23, l01, l23);
            *(uint32_t*)(sAh + off) = h01; *(uint32_t*)(sAh + off + 4) = h23;
            *(uint32_t*)(sAl + off) = l01; *(uint32_t*)(sAl + off + 4) = l23;
            split4(pb[i], h01, h23, l01, l23);
            *(uint32_t*)(sBh + off) = h01; *(uint32_t*)(sBh + off + 4) = h23;
            *(uint32_t*)(sBl + off) = l01; *(uint32_t*)(sBl + off + 4) = l23;
        }
    };

    // ---- prologue: chunk 0 --------------------------------------------------
    {
        float4 pa[4], pb[4];
        ldg_chunk(0, pa, pb);
        sts_chunk(bufc[0], pa, pb);
    }
    __syncthreads();

    // ldmatrix lane addressing
    const int l16 = lane & 15;
    const int lA_row = l16;                  // + warp_m*64 + mt*16
    const int lA_cg  = (lane >> 4) * 8;      // k-subgroup
    const int lB_row = l16 & 7;              // + warp_n*32 + nt*8
    const int lB_cg  = ((l16 >> 3) & 1) * 8;

    for (int c = 0; c < NC; c++) {
        int b = c & 1;
        float4 pa[4], pb[4];
        if (c + 1 < NC) ldg_chunk(c + 1, pa, pb);

        uint32_t sAh = smem_to_u32(bufc[b]);
        uint32_t sAl = sAh + TILEB;
        uint32_t sBh = sAh + 2 * TILEB;
        uint32_t sBl = sAh + 3 * TILEB;

#pragma unroll
        for (int ks = 0; ks < 2; ks++) {
            uint32_t ah[4][4], al[4][4], bh[4][2], bl[4][2];
#pragma unroll
            for (int mt = 0; mt < 4; mt++) {
                uint32_t off = ((uint32_t)((warp_m * 64 + mt * 16 + lA_row) * APAD
                                           + ks * 16 + lA_cg)) * 2;
                ldmx4(ah[mt][0], ah[mt][1], ah[mt][2], ah[mt][3], sAh + off);
                ldmx4(al[mt][0], al[mt][1], al[mt][2], al[mt][3], sAl + off);
            }
#pragma unroll
            for (int nt = 0; nt < 4; nt++) {
                uint32_t off = ((uint32_t)((warp_n * 32 + nt * 8 + lB_row) * APAD
                                           + ks * 16 + lB_cg)) * 2;
                ldmx2(bh[nt][0], bh[nt][1], sBh + off);
                ldmx2(bl[nt][0], bl[nt][1], sBl + off);
            }
#pragma unroll
            for (int mt = 0; mt < 4; mt++)
#pragma unroll
                for (int nt = 0; nt < 4; nt++) {
                    mma16816(acc[mt][nt], ah[mt], bh[nt]);
                    mma16816(acc[mt][nt], ah[mt], bl[nt]);
                    mma16816(acc[mt][nt], al[mt], bh[nt]);
                }
        }
        __syncthreads();
        if (c + 1 < NC) {
            sts_chunk(bufc[1 - b], pa, pb);
            __syncthreads();
        }
    }

    // ---- epilogue -----------------------------------------------------------
    const int r0    = lane >> 2;
    const int cpair = (lane & 3) * 2;
#pragma unroll
    for (int mt = 0; mt < 4; mt++) {
        int m = tile_m + warp_m * 64 + mt * 16 + r0;
#pragma unroll
        for (int nt = 0; nt < 4; nt++) {
            int n = tile_n + warp_n * 32 + nt * 8 + cpair;
            float2 bv = *(const float2*)(bias + n);
            float2 o0, o1;
            o0.x = acc[mt][nt][0] + bv.x;
            o0.y = acc[mt][nt][1] + bv.y;
            o1.x = acc[mt][nt][2] + bv.x;
            o1.y = acc[mt][nt][3] + bv.y;
            if (relu) {
                o0.x = fmaxf(o0.x, 0.f); o0.y = fmaxf(o0.y, 0.f);
                o1.x = fmaxf(o1.x, 0.f); o1.y = fmaxf(o1.y, 0.f);
            }
            *(float2*)(C + (size_t)m * N + n)       = o0;
            *(float2*)(C + (size_t)(m + 8) * N + n) = o1;
        }
    }
}

// ================= fp32 SGEMM (output head: N=64) ============================
#define BM 128
#define BN 128
#define BK 16
#define TM 8
#define TN 8

__global__ __launch_bounds__(256, 2)
void sgemm_bias(const float* __restrict__ A, const float* __restrict__ W,
                const float* __restrict__ bias, float* __restrict__ C,
                int M, int N, int K, int relu)
{
    __shared__ float As[BK][BM + 4];
    __shared__ float Bs[BK][BN + 4];

    const int bm  = blockIdx.y * BM;
    const int bn  = blockIdx.x * BN;
    const int tid = threadIdx.x;
    const int tx  = tid & 15;
    const int ty  = tid >> 4;

    float acc[TM][TN];
#pragma unroll
    for (int i = 0; i < TM; i++)
#pragma unroll
        for (int j = 0; j < TN; j++) acc[i][j] = 0.0f;

    for (int k0 = 0; k0 < K; k0 += BK) {
#pragma unroll
        for (int it = 0; it < 2; it++) {
            int idx = tid + it * 256;
            int row = idx >> 2;
            int c4  = (idx & 3) << 2;
            float4 v = *(const float4*)(A + (size_t)(bm + row) * K + k0 + c4);
            As[c4 + 0][row] = v.x; As[c4 + 1][row] = v.y;
            As[c4 + 2][row] = v.z; As[c4 + 3][row] = v.w;
        }
#pragma unroll
        for (int it = 0; it < 2; it++) {
            int idx = tid + it * 256;
            int row = idx >> 2;
            int c4  = (idx & 3) << 2;
            float4 v = make_float4(0.f, 0.f, 0.f, 0.f);
            if (bn + row < N)
                v = *(const float4*)(W + (size_t)(bn + row) * K + k0 + c4);
            Bs[c4 + 0][row] = v.x; Bs[c4 + 1][row] = v.y;
            Bs[c4 + 2][row] = v.z; Bs[c4 + 3][row] = v.w;
        }
        __syncthreads();

#pragma unroll
        for (int k = 0; k < BK; k++) {
            float a[TM], b[TN];
            float4 t0 = *(const float4*)&As[k][ty * TM];
            float4 t1 = *(const float4*)&As[k][ty * TM + 4];
            a[0]=t0.x; a[1]=t0.y; a[2]=t0.z; a[3]=t0.w;
            a[4]=t1.x; a[5]=t1.y; a[6]=t1.z; a[7]=t1.w;
            float4 u0 = *(const float4*)&Bs[k][tx * TN];
            float4 u1 = *(const float4*)&Bs[k][tx * TN + 4];
            b[0]=u0.x; b[1]=u0.y; b[2]=u0.z; b[3]=u0.w;
            b[4]=u1.x; b[5]=u1.y; b[6]=u1.z; b[7]=u1.w;
#pragma unroll
            for (int i = 0; i < TM; i++)
#pragma unroll
                for (int j = 0; j < TN; j++)
                    acc[i][j] = fmaf(a[i], b[j], acc[i][j]);
        }
        __syncthreads();
    }

#pragma unroll
    for (int i = 0; i < TM; i++) {
        int m = bm + ty * TM + i;
#pragma unroll
        for (int j4 = 0; j4 < 2; j4++) {
            int n = bn + tx * TN + j4 * 4;
            if (n < N) {
                float4 bv = *(const float4*)(bias + n);
                float4 o;
                o.x = acc[i][j4 * 4 + 0] + bv.x;
                o.y = acc[i][j4 * 4 + 1] + bv.y;
                o.z = acc[i][j4 * 4 + 2] + bv.z;
                o.w = acc[i][j4 * 4 + 3] + bv.w;
                if (relu) {
                    o.x = fmaxf(o.x, 0.f); o.y = fmaxf(o.y, 0.f);
                    o.z = fmaxf(o.z, 0.f); o.w = fmaxf(o.w, 0.f);
                }
                *(float4*)(C + (size_t)m * N + n) = o;
            }
        }
    }
}

// ================= banded attention ==========================================
__global__ __launch_bounds__(256)
void attn_kernel(const float* __restrict__ qkv, float* __restrict__ ctx)
{
    int w    = (blockIdx.x * blockDim.x + threadIdx.x) >> 5;
    int lane = threadIdx.x & 31;
    if (w >= TOK * NHEAD) return;
    int t = w >> 2;
    int h = w & 3;
    int s = t / B_;
    int b = t - s * B_;

    const float* qp = qkv + (size_t)t * (3 * H_) + h * DH;
    float ql[8];
#pragma unroll
    for (int i = 0; i < 8; i++) ql[i] = qp[lane + i * 32];

    int lo  = s - WIN; if (lo < 0) lo = 0;
    int cnt = s - lo + 1;

    float sc[WIN + 1];
#pragma unroll
    for (int j = 0; j <= WIN; j++) {
        sc[j] = -1e30f;
        if (j < cnt) {
            int tj = (lo + j) * B_ + b;
            const float* kp = qkv + (size_t)tj * (3 * H_) + H_ + h * DH;
            float p = 0.f;
#pragma unroll
            for (int i = 0; i < 8; i++) p = fmaf(ql[i], kp[lane + i * 32], p);
#pragma unroll
            for (int o = 16; o; o >>= 1) p += __shfl_xor_sync(0xFFFFFFFFu, p, o);
            sc[j] = p * 0.0625f;
        }
    }
    float m = sc[0];
#pragma unroll
    for (int j = 1; j <= WIN; j++) m = fmaxf(m, sc[j]);
    float e[WIN + 1];
    float se = 0.f;
#pragma unroll
    for (int j = 0; j <= WIN; j++) {
        e[j] = (j < cnt) ? __expf(sc[j] - m) : 0.f;
        se += e[j];
    }
    float inv = 1.f / se;

    float cx[8];
#pragma unroll
    for (int i = 0; i < 8; i++) cx[i] = 0.f;
    for (int j = 0; j < cnt; j++) {
        int tj = (lo + j) * B_ + b;
        const float* vp = qkv + (size_t)tj * (3 * H_) + 2 * H_ + h * DH;
        float a = e[j] * inv;
#pragma unroll
        for (int i = 0; i < 8; i++) cx[i] = fmaf(a, vp[lane + i * 32], cx[i]);
    }
    float* cp = ctx + (size_t)t * H_ + h * DH;
#pragma unroll
    for (int i = 0; i < 8; i++) cp[lane + i * 32] = cx[i];
}

// ================= residual + LayerNorm ======================================
__device__ __forceinline__ float block_sum(float v, float* red)
{
#pragma unroll
    for (int o = 16; o; o >>= 1) v += __shfl_xor_sync(0xFFFFFFFFu, v, o);
    int wid = threadIdx.x >> 5, lane = threadIdx.x & 31;
    if (lane == 0) red[wid] = v;
    __syncthreads();
    if (threadIdx.x < 32) {
        float r = (threadIdx.x < 8) ? red[threadIdx.x] : 0.f;
#pragma unroll
        for (int o = 4; o; o >>= 1) r += __shfl_xor_sync(0xFFFFFFFFu, r, o);
        if (threadIdx.x == 0) red[0] = r;
    }
    __syncthreads();
    float r = red[0];
    __syncthreads();
    return r;
}

__global__ __launch_bounds__(256)
void resid_ln_kernel(float* __restrict__ x, const float* __restrict__ delta,
                     const float* __restrict__ scale, const float* __restrict__ bias)
{
    __shared__ float red[8];
    int t   = blockIdx.x;
    int tid = threadIdx.x;
    size_t base = (size_t)t * H_ + tid * 4;

    float4 v = *(const float4*)(x + base);
    float4 d = *(const float4*)(delta + base);
    v.x += d.x; v.y += d.y; v.z += d.z; v.w += d.w;

    float s = v.x + v.y + v.z + v.w;
    float mean = block_sum(s, red) * (1.0f / H_);

    float dx = v.x - mean, dy = v.y - mean, dz = v.z - mean, dw = v.w - mean;
    float sq = dx * dx + dy * dy + dz * dz + dw * dw;
    float var = block_sum(sq, red) * (1.0f / H_);
    float rstd = rsqrtf(var + EPS);

    float4 sc = *(const float4*)(scale + tid * 4);
    float4 bi = *(const float4*)(bias + tid * 4);
    float4 o;
    o.x = dx * rstd * sc.x + bi.x;
    o.y = dy * rstd * sc.y + bi.y;
    o.z = dz * rstd * sc.z + bi.z;
    o.w = dw * rstd * sc.w + bi.w;
    *(float4*)(x + base) = o;
}

// ================= host orchestration ========================================
static inline void run_gemm_mma(const float* A, const float* W, const float* bias,
                                float* C, int M, int N, int K, int relu)
{
    static int attr_set = 0;
    if (!attr_set) {
        cudaFuncSetAttribute(gemm_mma, cudaFuncAttributeMaxDynamicSharedMemorySize, MM_SMEM);
        attr_set = 1;
    }
    dim3 grid(N / 128, M / 128);
    gemm_mma<<<grid, 256, MM_SMEM>>>(A, W, bias, C, M, N, K, relu);
}

static inline void run_gemm_f32(const float* A, const float* W, const float* bias,
                                float* C, int M, int N, int K, int relu)
{
    dim3 grid((N + BN - 1) / BN, (M + BM - 1) / BM);
    sgemm_bias<<<grid, 256>>>(A, W, bias, C, M, N, K, relu);
}

extern "C" void kernel_launch(void* const* d_in, const int* in_sizes, int n_in,
                              void* d_out, int out_size)
{
    const float* src   = (const float*)d_in[0];
    const float* Wenc  = (const float*)d_in[1];
    const float* benc  = (const float*)d_in[2];
    const float* Wqkv  = (const float*)d_in[3];
    const float* bqkv  = (const float*)d_in[4];
    const float* Wo    = (const float*)d_in[5];
    const float* bo    = (const float*)d_in[6];
    const float* W1    = (const float*)d_in[7];
    const float* b1    = (const float*)d_in[8];
    const float* W2    = (const float*)d_in[9];
    const float* b2    = (const float*)d_in[10];
    const float* ln1_s = (const float*)d_in[11];
    const float* ln1_b = (const float*)d_in[12];
    const float* ln2_s = (const float*)d_in[13];
    const float* ln2_b = (const float*)d_in[14];
    const float* Wout  = (const float*)d_in[15];
    const float* bout  = (const float*)d_in[16];
    float* out = (float*)d_out;

    float *x, *qkv, *ctx, *tmp, *h1;
    cudaGetSymbolAddress((void**)&x,   g_x);
    cudaGetSymbolAddress((void**)&qkv, g_qkv);
    cudaGetSymbolAddress((void**)&ctx, g_ctx);
    cudaGetSymbolAddress((void**)&tmp, g_tmp);
    cudaGetSymbolAddress((void**)&h1,  g_h1);

    // encoder: x = src @ Wenc^T + benc   (K=64, runs on mma path: 64%32==0)
    run_gemm_mma(src, Wenc, benc, x, TOK, H_, INDIM, 0);

    for (int l = 0; l < L_; l++) {
        const float* Wqkv_l = Wqkv + (size_t)l * 3 * H_ * H_;
        const float* bqkv_l = bqkv + (size_t)l * 3 * H_;
        const float* Wo_l   = Wo   + (size_t)l * H_ * H_;
        const float* bo_l   = bo   + (size_t)l * H_;
        const float* W1_l   = W1   + (size_t)l * DFF_ * H_;
        const float* b1_l   = b1   + (size_t)l * DFF_;
        const float* W2_l   = W2   + (size_t)l * H_ * DFF_;
        const float* b2_l   = b2   + (size_t)l * H_;

        run_gemm_mma(x, Wqkv_l, bqkv_l, qkv, TOK, 3 * H_, H_, 0);
        attn_kernel<<<(TOK * NHEAD) / 8, 256>>>(qkv, ctx);
        run_gemm_mma(ctx, Wo_l, bo_l, tmp, TOK, H_, H_, 0);
        resid_ln_kernel<<<TOK, 256>>>(x, tmp, ln1_s + (size_t)l * H_, ln1_b + (size_t)l * H_);
        run_gemm_mma(x, W1_l, b1_l, h1, TOK, DFF_, H_, 1);
        run_gemm_mma(h1, W2_l, b2_l, tmp, TOK, H_, DFF_, 0);
        resid_ln_kernel<<<TOK, 256>>>(x, tmp, ln2_s + (size_t)l * H_, ln2_b + (size_t)l * H_);
    }

    // out = x @ Wout^T + bout   (N=64 -> fp32 path with guards)
    run_gemm_f32(x, Wout, bout, out, TOK, OUTD, H_, 0);
}

// round 5
// speedup vs baseline: 1.4562x; 1.2850x over previous
#include <cuda_runtime.h>
#include <cuda_bf16.h>
#include <cstdint>
#include <cstddef>

#define S_    2048
#define B_    4
#define INDIM 64
#define H_    1024
#define DFF_  1024
#define OUTD  64
#define L_    3
#define NHEAD 4
#define DH    (H_ / NHEAD)   // 256
#define WIN   4
#define TOK   (S_ * B_)      // 8192
#define EPS   1e-5f
#define K3H   (3 * H_)       // 3072 (interleaved K for K=H)
#define K3IN  (3 * INDIM)    // 192

// ---------------- scratch (static device globals) -----------------------------
__device__ float g_x[TOK * H_];
__device__ float g_qkv[TOK * 3 * H_];
__device__ float g_ctx[TOK * H_];
__device__ float g_tmp[TOK * H_];

__device__ __align__(256) __nv_bfloat16 g_src3[TOK * K3IN];
__device__ __align__(256) __nv_bfloat16 g_x3[TOK * K3H];
__device__ __align__(256) __nv_bfloat16 g_ctx3[TOK * K3H];
__device__ __align__(256) __nv_bfloat16 g_h13[TOK * K3H];
__device__ __align__(256) __nv_bfloat16 g_wenc3[H_ * K3IN];
__device__ __align__(256) __nv_bfloat16 g_wqkv3[L_ * 3 * H_ * K3H];
__device__ __align__(256) __nv_bfloat16 g_wo3[L_ * H_ * K3H];
__device__ __align__(256) __nv_bfloat16 g_w13[L_ * DFF_ * K3H];
__device__ __align__(256) __nv_bfloat16 g_w23[L_ * H_ * K3H];

// ---------------- helpers -----------------------------------------------------
__device__ __forceinline__ uint32_t smem_to_u32(const void* p) {
    uint32_t a;
    asm("{ .reg .u64 t; cvta.to.shared.u64 t, %1; cvt.u32.u64 %0, t; }"
        : "=r"(a) : "l"(p));
    return a;
}
__device__ __forceinline__ uint32_t pack_bf16x2(__nv_bfloat16 a, __nv_bfloat16 b) {
    __nv_bfloat162 t = __halves2bfloat162(a, b);
    return *reinterpret_cast<uint32_t*>(&t);
}
__device__ __forceinline__ void split1(float v, __nv_bfloat16& h, __nv_bfloat16& l) {
    h = __float2bfloat16(v);
    l = __float2bfloat16(v - __bfloat162float(h));
}
__device__ __forceinline__ void cp_async16(uint32_t dst, const void* src) {
    asm volatile("cp.async.cg.shared.global [%0], [%1], 16;"
                 :: "r"(dst), "l"(src) : "memory");
}
__device__ __forceinline__ void cp_commit() {
    asm volatile("cp.async.commit_group;" ::: "memory");
}
__device__ __forceinline__ void cp_wait2() {
    asm volatile("cp.async.wait_group 2;" ::: "memory");
}
__device__ __forceinline__ void ldmx4(uint32_t& r0, uint32_t& r1,
                                      uint32_t& r2, uint32_t& r3, uint32_t a) {
    asm volatile("ldmatrix.sync.aligned.m8n8.x4.shared.b16 {%0,%1,%2,%3}, [%4];"
                 : "=r"(r0), "=r"(r1), "=r"(r2), "=r"(r3) : "r"(a));
}
__device__ __forceinline__ void ldmx2(uint32_t& r0, uint32_t& r1, uint32_t a) {
    asm volatile("ldmatrix.sync.aligned.m8n8.x2.shared.b16 {%0,%1}, [%2];"
                 : "=r"(r0), "=r"(r1) : "r"(a));
}
__device__ __forceinline__ void mma16816(float* d, const uint32_t* a, const uint32_t* b) {
    asm volatile("mma.sync.aligned.m16n8k16.row.col.f32.bf16.bf16.f32 "
                 "{%0,%1,%2,%3}, {%4,%5,%6,%7}, {%8,%9}, {%0,%1,%2,%3};"
                 : "+f"(d[0]), "+f"(d[1]), "+f"(d[2]), "+f"(d[3])
                 : "r"(a[0]), "r"(a[1]), "r"(a[2]), "r"(a[3]), "r"(b[0]), "r"(b[1]));
}

// ---------------- conversion: fp32 -> interleaved bf16x3 ----------------------
// pattern 0 (activation / A side): per k -> [hi, hi, lo]
// pattern 1 (weight / B side):     per k -> [hi, lo, hi]
__global__ void conv_split(const float* __restrict__ in, __nv_bfloat16* __restrict__ out,
                           int npairs, int pattern)
{
    int i = blockIdx.x * blockDim.x + threadIdx.x;
    if (i >= npairs) return;
    float f0 = in[2 * i], f1 = in[2 * i + 1];
    __nv_bfloat16 h0, l0, h1, l1;
    split1(f0, h0, l0);
    split1(f1, h1, l1);
    uint32_t* o = reinterpret_cast<uint32_t*>(out) + 3 * (size_t)i;
    if (pattern == 0) {
        o[0] = pack_bf16x2(h0, h0); o[1] = pack_bf16x2(l0, h1); o[2] = pack_bf16x2(h1, l1);
    } else {
        o[0] = pack_bf16x2(h0, l0); o[1] = pack_bf16x2(h0, h1); o[2] = pack_bf16x2(l1, h1);
    }
}

// ---------------- bf16 HMMA GEMM over interleaved K3 --------------------------
// C[M,N] = A3[M,K3] @ B3[N,K3]^T + bias.  M%128==0, N%128==0, K3%64==0, K3/64>=3.
// mode bits: 1 = write fp32 C, 2 = write bf16-interleaved C3 (A-pattern), 4 = relu
#define GSTG  3
#define GSB   32768                     // stage bytes: A 16KB + B 16KB
#define GSMEM (GSTG * GSB)              // 98304

__global__ __launch_bounds__(512, 1)
void gemm_bf16(const __nv_bfloat16* __restrict__ A3, const __nv_bfloat16* __restrict__ B3,
               const float* __restrict__ bias, float* __restrict__ C,
               __nv_bfloat16* __restrict__ C3,
               int M, int N, int K3, int mode)
{
    extern __shared__ char smem[];
    const uint32_t sb = smem_to_u32(smem);
    const int tid  = threadIdx.x;
    const int wid  = tid >> 5;
    const int lane = tid & 31;
    const int warp_m = wid >> 2;        // 0..3 -> 32-row block
    const int warp_n = wid & 3;         // 0..3 -> 32-col block
    const int tile_m = blockIdx.y * 128;
    const int tile_n = blockIdx.x * 128;
    const int NC = K3 >> 6;

    // cp.async addressing: thread handles 16B units {tid, tid+512} of each operand
    const int ru = tid >> 3;            // row 0..63
    const int cu = tid & 7;             // 16B unit within 128B row
    const __nv_bfloat16* gA0 = A3 + (size_t)(tile_m + ru) * K3 + cu * 8;
    const __nv_bfloat16* gA1 = gA0 + (size_t)64 * K3;
    const __nv_bfloat16* gB0 = B3 + (size_t)(tile_n + ru) * K3 + cu * 8;
    const __nv_bfloat16* gB1 = gB0 + (size_t)64 * K3;
    const uint32_t sAoff = (uint32_t)(ru * 128 + ((cu ^ (ru & 7)) << 4));

    float acc[2][4][4];
#pragma unroll
    for (int i = 0; i < 2; i++)
#pragma unroll
        for (int j = 0; j < 4; j++)
#pragma unroll
            for (int k = 0; k < 4; k++) acc[i][j][k] = 0.f;

    auto issue = [&](int stage, int chunk) {
        uint32_t s = sb + stage * GSB;
        size_t koff = (size_t)chunk * 64;
        cp_async16(s + sAoff,                gA0 + koff);
        cp_async16(s + sAoff + 8192,         gA1 + koff);
        cp_async16(s + sAoff + 16384,        gB0 + koff);
        cp_async16(s + sAoff + 16384 + 8192, gB1 + koff);
    };

    // prologue
    issue(0, 0); cp_commit();
    issue(1, 1); cp_commit();
    issue(2, 2); cp_commit();

    const int l16 = lane & 15;
    const int a_hi = lane >> 4;          // 0/1: k-subgroup unit for A
    const int b_hi = (l16 >> 3) & 1;     // 0/1 for B
    const int rA_base = warp_m * 32 + l16;      // + mt*16
    const int rB_base = warp_n * 32 + (l16 & 7);// + nt*8

    for (int c = 0; c < NC; c++) {
        cp_wait2();
        __syncthreads();
        uint32_t sA = sb + (c % 3) * GSB;
        uint32_t sB = sA + 16384;
#pragma unroll
        for (int ks = 0; ks < 4; ks++) {
            uint32_t a[2][4], b[4][2];
#pragma unroll
            for (int mt = 0; mt < 2; mt++) {
                int r = rA_base + mt * 16;
                uint32_t cunit = (uint32_t)((ks * 2 + a_hi) ^ (r & 7));
                ldmx4(a[mt][0], a[mt][1], a[mt][2], a[mt][3],
                      sA + (uint32_t)r * 128 + (cunit << 4));
            }
#pragma unroll
            for (int nt = 0; nt < 4; nt++) {
                int r = rB_base + nt * 8;
                uint32_t cunit = (uint32_t)((ks * 2 + b_hi) ^ (r & 7));
                ldmx2(b[nt][0], b[nt][1], sB + (uint32_t)r * 128 + (cunit << 4));
            }
#pragma unroll
            for (int mt = 0; mt < 2; mt++)
#pragma unroll
                for (int nt = 0; nt < 4; nt++)
                    mma16816(acc[mt][nt], a[mt], b[nt]);
        }
        __syncthreads();
        if (c + 3 < NC) issue(c % 3, c + 3);
        cp_commit();
    }

    // epilogue
    const int r0    = lane >> 2;
    const int cpair = (lane & 3) * 2;
#pragma unroll
    for (int mt = 0; mt < 2; mt++) {
#pragma unroll
        for (int nt = 0; nt < 4; nt++) {
            int n = tile_n + warp_n * 32 + nt * 8 + cpair;
            float2 bv = *(const float2*)(bias + n);
            int m0 = tile_m + warp_m * 32 + mt * 16 + r0;
            float v[2][2];
            v[0][0] = acc[mt][nt][0] + bv.x; v[0][1] = acc[mt][nt][1] + bv.y;
            v[1][0] = acc[mt][nt][2] + bv.x; v[1][1] = acc[mt][nt][3] + bv.y;
            if (mode & 4) {
#pragma unroll
                for (int i = 0; i < 2; i++) {
                    v[i][0] = fmaxf(v[i][0], 0.f); v[i][1] = fmaxf(v[i][1], 0.f);
                }
            }
            if (mode & 1) {
                *(float2*)(C + (size_t)m0 * N + n)       = make_float2(v[0][0], v[0][1]);
                *(float2*)(C + (size_t)(m0 + 8) * N + n) = make_float2(v[1][0], v[1][1]);
            }
            if (mode & 2) {
#pragma unroll
                for (int i = 0; i < 2; i++) {
                    int m = m0 + i * 8;
                    __nv_bfloat16 h0, l0, h1, l1;
                    split1(v[i][0], h0, l0);
                    split1(v[i][1], h1, l1);
                    uint32_t* o = reinterpret_cast<uint32_t*>(C3)
                                + ((3 * ((size_t)m * N + n)) >> 1);
                    o[0] = pack_bf16x2(h0, h0);
                    o[1] = pack_bf16x2(l0, h1);
                    o[2] = pack_bf16x2(h1, l1);
                }
            }
        }
    }
}

// ---------------- fp32 SGEMM (output head: N=64) ------------------------------
#define BM 128
#define BN 128
#define BK 16
#define TM 8
#define TN 8

__global__ __launch_bounds__(256, 2)
void sgemm_bias(const float* __restrict__ A, const float* __restrict__ W,
                const float* __restrict__ bias, float* __restrict__ C,
                int M, int N, int K, int relu)
{
    __shared__ float As[BK][BM + 4];
    __shared__ float Bs[BK][BN + 4];

    const int bm  = blockIdx.y * BM;
    const int bn  = blockIdx.x * BN;
    const int tid = threadIdx.x;
    const int tx  = tid & 15;
    const int ty  = tid >> 4;

    float acc[TM][TN];
#pragma unroll
    for (int i = 0; i < TM; i++)
#pragma unroll
        for (int j = 0; j < TN; j++) acc[i][j] = 0.0f;

    for (int k0 = 0; k0 < K; k0 += BK) {
#pragma unroll
        for (int it = 0; it < 2; it++) {
            int idx = tid + it * 256;
            int row = idx >> 2;
            int c4  = (idx & 3) << 2;
            float4 v = *(const float4*)(A + (size_t)(bm + row) * K + k0 + c4);
            As[c4 + 0][row] = v.x; As[c4 + 1][row] = v.y;
            As[c4 + 2][row] = v.z; As[c4 + 3][row] = v.w;
        }
#pragma unroll
        for (int it = 0; it < 2; it++) {
            int idx = tid + it * 256;
            int row = idx >> 2;
            int c4  = (idx & 3) << 2;
            float4 v = make_float4(0.f, 0.f, 0.f, 0.f);
            if (bn + row < N)
                v = *(const float4*)(W + (size_t)(bn + row) * K + k0 + c4);
            Bs[c4 + 0][row] = v.x; Bs[c4 + 1][row] = v.y;
            Bs[c4 + 2][row] = v.z; Bs[c4 + 3][row] = v.w;
        }
        __syncthreads();

#pragma unroll
        for (int k = 0; k < BK; k++) {
            float a[TM], b[TN];
            float4 t0 = *(const float4*)&As[k][ty * TM];
            float4 t1 = *(const float4*)&As[k][ty * TM + 4];
            a[0]=t0.x; a[1]=t0.y; a[2]=t0.z; a[3]=t0.w;
            a[4]=t1.x; a[5]=t1.y; a[6]=t1.z; a[7]=t1.w;
            float4 u0 = *(const float4*)&Bs[k][tx * TN];
            float4 u1 = *(const float4*)&Bs[k][tx * TN + 4];
            b[0]=u0.x; b[1]=u0.y; b[2]=u0.z; b[3]=u0.w;
            b[4]=u1.x; b[5]=u1.y; b[6]=u1.z; b[7]=u1.w;
#pragma unroll
            for (int i = 0; i < TM; i++)
#pragma unroll
                for (int j = 0; j < TN; j++)
                    acc[i][j] = fmaf(a[i], b[j], acc[i][j]);
        }
        __syncthreads();
    }

#pragma unroll
    for (int i = 0; i < TM; i++) {
        int m = bm + ty * TM + i;
#pragma unroll
        for (int j4 = 0; j4 < 2; j4++) {
            int n = bn + tx * TN + j4 * 4;
            if (n < N) {
                float4 bv = *(const float4*)(bias + n);
                float4 o;
                o.x = acc[i][j4 * 4 + 0] + bv.x;
                o.y = acc[i][j4 * 4 + 1] + bv.y;
                o.z = acc[i][j4 * 4 + 2] + bv.z;
                o.w = acc[i][j4 * 4 + 3] + bv.w;
                if (relu) {
                    o.x = fmaxf(o.x, 0.f); o.y = fmaxf(o.y, 0.f);
                    o.z = fmaxf(o.z, 0.f); o.w = fmaxf(o.w, 0.f);
                }
                *(float4*)(C + (size_t)m * N + n) = o;
            }
        }
    }
}

// ---------------- banded attention --------------------------------------------
__global__ __launch_bounds__(256)
void attn_kernel(const float* __restrict__ qkv, float* __restrict__ ctx)
{
    int w    = (blockIdx.x * blockDim.x + threadIdx.x) >> 5;
    int lane = threadIdx.x & 31;
    if (w >= TOK * NHEAD) return;
    int t = w >> 2;
    int h = w & 3;
    int s = t / B_;
    int b = t - s * B_;

    const float* qp = qkv + (size_t)t * (3 * H_) + h * DH;
    float ql[8];
#pragma unroll
    for (int i = 0; i < 8; i++) ql[i] = qp[lane + i * 32];

    int lo  = s - WIN; if (lo < 0) lo = 0;
    int cnt = s - lo + 1;

    float sc[WIN + 1];
#pragma unroll
    for (int j = 0; j <= WIN; j++) {
        sc[j] = -1e30f;
        if (j < cnt) {
            int tj = (lo + j) * B_ + b;
            const float* kp = qkv + (size_t)tj * (3 * H_) + H_ + h * DH;
            float p = 0.f;
#pragma unroll
            for (int i = 0; i < 8; i++) p = fmaf(ql[i], kp[lane + i * 32], p);
#pragma unroll
            for (int o = 16; o; o >>= 1) p += __shfl_xor_sync(0xFFFFFFFFu, p, o);
            sc[j] = p * 0.0625f;
        }
    }
    float m = sc[0];
#pragma unroll
    for (int j = 1; j <= WIN; j++) m = fmaxf(m, sc[j]);
    float e[WIN + 1];
    float se = 0.f;
#pragma unroll
    for (int j = 0; j <= WIN; j++) {
        e[j] = (j < cnt) ? __expf(sc[j] - m) : 0.f;
        se += e[j];
    }
    float inv = 1.f / se;

    float cx[8];
#pragma unroll
    for (int i = 0; i < 8; i++) cx[i] = 0.f;
    for (int j = 0; j < cnt; j++) {
        int tj = (lo + j) * B_ + b;
        const float* vp = qkv + (size_t)tj * (3 * H_) + 2 * H_ + h * DH;
        float a = e[j] * inv;
#pragma unroll
        for (int i = 0; i < 8; i++) cx[i] = fmaf(a, vp[lane + i * 32], cx[i]);
    }
    float* cp = ctx + (size_t)t * H_ + h * DH;
#pragma unroll
    for (int i = 0; i < 8; i++) cp[lane + i * 32] = cx[i];
}

// ---------------- residual + LayerNorm (dual write: fp32 + bf16x3) ------------
__device__ __forceinline__ float block_sum(float v, float* red)
{
#pragma unroll
    for (int o = 16; o; o >>= 1) v += __shfl_xor_sync(0xFFFFFFFFu, v, o);
    int wid = threadIdx.x >> 5, lane = threadIdx.x & 31;
    if (lane == 0) red[wid] = v;
    __syncthreads();
    if (threadIdx.x < 32) {
        float r = (threadIdx.x < 8) ? red[threadIdx.x] : 0.f;
#pragma unroll
        for (int o = 4; o; o >>= 1) r += __shfl_xor_sync(0xFFFFFFFFu, r, o);
        if (threadIdx.x == 0) red[0] = r;
    }
    __syncthreads();
    float r = red[0];
    __syncthreads();
    return r;
}

__global__ __launch_bounds__(256)
void resid_ln_kernel(float* __restrict__ x, const float* __restrict__ delta,
                     const float* __restrict__ scale, const float* __restrict__ bias,
                     __nv_bfloat16* __restrict__ x3)
{
    __shared__ float red[8];
    int t   = blockIdx.x;
    int tid = threadIdx.x;
    size_t base = (size_t)t * H_ + tid * 4;

    float4 v = *(const float4*)(x + base);
    float4 d = *(const float4*)(delta + base);
    v.x += d.x; v.y += d.y; v.z += d.z; v.w += d.w;

    float s = v.x + v.y + v.z + v.w;
    float mean = block_sum(s, red) * (1.0f / H_);

    float dx = v.x - mean, dy = v.y - mean, dz = v.z - mean, dw = v.w - mean;
    float sq = dx * dx + dy * dy + dz * dz + dw * dw;
    float var = block_sum(sq, red) * (1.0f / H_);
    float rstd = rsqrtf(var + EPS);

    float4 sc = *(const float4*)(scale + tid * 4);
    float4 bi = *(const float4*)(bias + tid * 4);
    float4 o;
    o.x = dx * rstd * sc.x + bi.x;
    o.y = dy * rstd * sc.y + bi.y;
    o.z = dz * rstd * sc.z + bi.z;
    o.w = dw * rstd * sc.w + bi.w;
    *(float4*)(x + base) = o;

    // interleaved bf16x3 (A-pattern) write
    __nv_bfloat16 h0, l0, h1, l1, h2, l2, h3, l3;
    split1(o.x, h0, l0); split1(o.y, h1, l1);
    split1(o.z, h2, l2); split1(o.w, h3, l3);
    uint32_t* o3 = reinterpret_cast<uint32_t*>(x3) + (size_t)t * (3 * H_ / 2) + tid * 6;
    o3[0] = pack_bf16x2(h0, h0); o3[1] = pack_bf16x2(l0, h1); o3[2] = pack_bf16x2(h1, l1);
    o3[3] = pack_bf16x2(h2, h2); o3[4] = pack_bf16x2(l2, h3); o3[5] = pack_bf16x2(h3, l3);
}

// ---------------- host orchestration ------------------------------------------
static inline void run_conv(const float* in, __nv_bfloat16* out, size_t nelem, int pattern)
{
    int npairs = (int)(nelem / 2);
    conv_split<<<(npairs + 255) / 256, 256>>>(in, out, npairs, pattern);
}

static inline void run_gemm_bf16(const __nv_bfloat16* A3, const __nv_bfloat16* B3,
                                 const float* bias, float* C, __nv_bfloat16* C3,
                                 int M, int N, int K3, int mode)
{
    static int attr_set = 0;
    if (!attr_set) {
        cudaFuncSetAttribute(gemm_bf16, cudaFuncAttributeMaxDynamicSharedMemorySize, GSMEM);
        attr_set = 1;
    }
    dim3 grid(N / 128, M / 128);
    gemm_bf16<<<grid, 512, GSMEM>>>(A3, B3, bias, C, C3, M, N, K3, mode);
}

extern "C" void kernel_launch(void* const* d_in, const int* in_sizes, int n_in,
                              void* d_out, int out_size)
{
    const float* src   = (const float*)d_in[0];
    const float* Wenc  = (const float*)d_in[1];
    const float* benc  = (const float*)d_in[2];
    const float* Wqkv  = (const float*)d_in[3];
    const float* bqkv  = (const float*)d_in[4];
    const float* Wo    = (const float*)d_in[5];
    const float* bo    = (const float*)d_in[6];
    const float* W1    = (const float*)d_in[7];
    const float* b1    = (const float*)d_in[8];
    const float* W2    = (const float*)d_in[9];
    const float* b2    = (const float*)d_in[10];
    const float* ln1_s = (const float*)d_in[11];
    const float* ln1_b = (const float*)d_in[12];
    const float* ln2_s = (const float*)d_in[13];
    const float* ln2_b = (const float*)d_in[14];
    const float* Wout  = (const float*)d_in[15];
    const float* bout  = (const float*)d_in[16];
    float* out = (float*)d_out;

    float *x, *qkv, *ctx, *tmp;
    __nv_bfloat16 *src3, *x3, *ctx3, *h13, *wenc3, *wqkv3, *wo3, *w13, *w23;
    cudaGetSymbolAddress((void**)&x,    g_x);
    cudaGetSymbolAddress((void**)&qkv,  g_qkv);
    cudaGetSymbolAddress((void**)&ctx,  g_ctx);
    cudaGetSymbolAddress((void**)&tmp,  g_tmp);
    cudaGetSymbolAddress((void**)&src3, g_src3);
    cudaGetSymbolAddress((void**)&x3,   g_x3);
    cudaGetSymbolAddress((void**)&ctx3, g_ctx3);
    cudaGetSymbolAddress((void**)&h13,  g_h13);
    cudaGetSymbolAddress((void**)&wenc3, g_wenc3);
    cudaGetSymbolAddress((void**)&wqkv3, g_wqkv3);
    cudaGetSymbolAddress((void**)&wo3,   g_wo3);
    cudaGetSymbolAddress((void**)&w13,   g_w13);
    cudaGetSymbolAddress((void**)&w23,   g_w23);

    // weight + src conversions
    run_conv(src,  src3,  (size_t)TOK * INDIM, 0);
    run_conv(Wenc, wenc3, (size_t)H_ * INDIM, 1);
    run_conv(Wqkv, wqkv3, (size_t)L_ * 3 * H_ * H_, 1);
    run_conv(Wo,   wo3,   (size_t)L_ * H_ * H_, 1);
    run_conv(W1,   w13,   (size_t)L_ * DFF_ * H_, 1);
    run_conv(W2,   w23,   (size_t)L_ * H_ * DFF_, 1);

    // encoder: x = src @ Wenc^T + benc  (writes fp32 x and bf16x3 x3)
    run_gemm_bf16(src3, wenc3, benc, x, x3, TOK, H_, K3IN, 1 | 2);

    for (int l = 0; l < L_; l++) {
        const __nv_bfloat16* wqkv3_l = wqkv3 + (size_t)l * 3 * H_ * K3H;
        const __nv_bfloat16* wo3_l   = wo3   + (size_t)l * H_ * K3H;
        const __nv_bfloat16* w13_l   = w13   + (size_t)l * DFF_ * K3H;
        const __nv_bfloat16* w23_l   = w23   + (size_t)l * H_ * K3H;
        const float* bqkv_l = bqkv + (size_t)l * 3 * H_;
        const float* bo_l   = bo   + (size_t)l * H_;
        const float* b1_l   = b1   + (size_t)l * DFF_;
        const float* b2_l   = b2   + (size_t)l * H_;

        // qkv = x @ Wqkv^T + bqkv (fp32 out for attention)
        run_gemm_bf16(x3, wqkv3_l, bqkv_l, qkv, nullptr, TOK, 3 * H_, K3H, 1);
        // banded attention
        attn_kernel<<<(TOK * NHEAD) / 8, 256>>>(qkv, ctx);
        run_conv(ctx, ctx3, (size_t)TOK * H_, 0);
        // attn_out = ctx @ Wo^T + bo
        run_gemm_bf16(ctx3, wo3_l, bo_l, tmp, nullptr, TOK, H_, K3H, 1);
        // x = LN(x + attn_out), dual write x3
        resid_ln_kernel<<<TOK, 256>>>(x, tmp, ln1_s + (size_t)l * H_, ln1_b + (size_t)l * H_, x3);
        // h1 = relu(x @ W1^T + b1) -> bf16x3 only
        run_gemm_bf16(x3, w13_l, b1_l, nullptr, h13, TOK, DFF_, K3H, 2 | 4);
        // ff = h1 @ W2^T + b2
        run_gemm_bf16(h13, w23_l, b2_l, tmp, nullptr, TOK, H_, K3H, 1);
        // x = LN(x + ff), dual write x3
        resid_ln_kernel<<<TOK, 256>>>(x, tmp, ln2_s + (size_t)l * H_, ln2_b + (size_t)l * H_, x3);
    }

    // out = x @ Wout^T + bout   (N=64 -> fp32 path)
    dim3 grid((OUTD + BN - 1) / BN, TOK / BM);
    sgemm_bias<<<grid, 256>>>(x, Wout, bout, out, TOK, OUTD, H_, 0);
}

// round 10
// speedup vs baseline: 2.5306x; 1.7378x over previous
#include <cuda_runtime.h>
#include <cuda_bf16.h>
#include <cstdint>
#include <cstddef>

#define S_    2048
#define B_    4
#define INDIM 64
#define H_    1024
#define DFF_  1024
#define OUTD  64
#define L_    3
#define NHEAD 4
#define DH    (H_ / NHEAD)   // 256
#define WIN   4
#define TOK   (S_ * B_)      // 8192
#define EPS   1e-5f
#define K3H   (3 * H_)       // 3072
#define K3IN  (3 * INDIM)    // 192

// ---------------- scratch (static device globals) -----------------------------
__device__ float g_x[TOK * H_];
__device__ float g_qkv[TOK * 3 * H_];
__device__ float g_tmp[TOK * H_];

__device__ __align__(256) __nv_bfloat16 g_src3[TOK * K3IN];
__device__ __align__(256) __nv_bfloat16 g_x3[TOK * K3H];
__device__ __align__(256) __nv_bfloat16 g_ctx3[TOK * K3H];
__device__ __align__(256) __nv_bfloat16 g_h13[TOK * K3H];
__device__ __align__(256) __nv_bfloat16 g_wenc3[H_ * K3IN];
__device__ __align__(256) __nv_bfloat16 g_wqkv3[L_ * 3 * H_ * K3H];
__device__ __align__(256) __nv_bfloat16 g_wo3[L_ * H_ * K3H];
__device__ __align__(256) __nv_bfloat16 g_w13[L_ * DFF_ * K3H];
__device__ __align__(256) __nv_bfloat16 g_w23[L_ * H_ * K3H];

// ---------------- helpers -----------------------------------------------------
__device__ __forceinline__ uint32_t smem_to_u32(const void* p) {
    uint32_t a;
    asm("{ .reg .u64 t; cvta.to.shared.u64 t, %1; cvt.u32.u64 %0, t; }"
        : "=r"(a) : "l"(p));
    return a;
}
__device__ __forceinline__ uint32_t pack_bf16x2(__nv_bfloat16 a, __nv_bfloat16 b) {
    __nv_bfloat162 t = __halves2bfloat162(a, b);
    return *reinterpret_cast<uint32_t*>(&t);
}
__device__ __forceinline__ void split1(float v, __nv_bfloat16& h, __nv_bfloat16& l) {
    h = __float2bfloat16(v);
    l = __float2bfloat16(v - __bfloat162float(h));
}
__device__ __forceinline__ void cp_async16(uint32_t dst, const void* src) {
    asm volatile("cp.async.cg.shared.global [%0], [%1], 16;"
                 :: "r"(dst), "l"(src) : "memory");
}
__device__ __forceinline__ void cp_commit() {
    asm volatile("cp.async.commit_group;" ::: "memory");
}
__device__ __forceinline__ void cp_wait2() {
    asm volatile("cp.async.wait_group 2;" ::: "memory");
}
__device__ __forceinline__ void ldmx4(uint32_t* r, uint32_t a) {
    asm volatile("ldmatrix.sync.aligned.m8n8.x4.shared.b16 {%0,%1,%2,%3}, [%4];"
                 : "=r"(r[0]), "=r"(r[1]), "=r"(r[2]), "=r"(r[3]) : "r"(a));
}
__device__ __forceinline__ void mma16816(float* d, const uint32_t* a,
                                         uint32_t b0, uint32_t b1) {
    asm volatile("mma.sync.aligned.m16n8k16.row.col.f32.bf16.bf16.f32 "
                 "{%0,%1,%2,%3}, {%4,%5,%6,%7}, {%8,%9}, {%0,%1,%2,%3};"
                 : "+f"(d[0]), "+f"(d[1]), "+f"(d[2]), "+f"(d[3])
                 : "r"(a[0]), "r"(a[1]), "r"(a[2]), "r"(a[3]), "r"(b0), "r"(b1));
}

// ---------------- conversion: fp32 -> interleaved bf16x3 ----------------------
// pattern 0 (A side): per k -> [hi, hi, lo]; pattern 1 (B side): [hi, lo, hi]
__device__ __forceinline__ void conv_pair(const float* in, uint32_t* o, int pattern) {
    float f0 = in[0], f1 = in[1];
    __nv_bfloat16 h0, l0, h1, l1;
    split1(f0, h0, l0);
    split1(f1, h1, l1);
    if (pattern == 0) {
        o[0] = pack_bf16x2(h0, h0); o[1] = pack_bf16x2(l0, h1); o[2] = pack_bf16x2(h1, l1);
    } else {
        o[0] = pack_bf16x2(h0, l0); o[1] = pack_bf16x2(h0, h1); o[2] = pack_bf16x2(l1, h1);
    }
}

__global__ void conv_split(const float* __restrict__ in, __nv_bfloat16* __restrict__ out,
                           int npairs, int pattern)
{
    int i = blockIdx.x * blockDim.x + threadIdx.x;
    if (i >= npairs) return;
    conv_pair(in + 2 * (size_t)i, reinterpret_cast<uint32_t*>(out) + 3 * (size_t)i, pattern);
}

// three weight tensors in one launch (all same size, pattern 1)
__global__ void conv_split3(const float* __restrict__ a, const float* __restrict__ b,
                            const float* __restrict__ c,
                            __nv_bfloat16* __restrict__ oa, __nv_bfloat16* __restrict__ ob,
                            __nv_bfloat16* __restrict__ oc, int npairs)
{
    int i = blockIdx.x * blockDim.x + threadIdx.x;
    if (i >= npairs) return;
    const float* in = (blockIdx.y == 0) ? a : (blockIdx.y == 1) ? b : c;
    __nv_bfloat16* out = (blockIdx.y == 0) ? oa : (blockIdx.y == 1) ? ob : oc;
    conv_pair(in + 2 * (size_t)i, reinterpret_cast<uint32_t*>(out) + 3 * (size_t)i, 1);
}

// ---------------- bf16 HMMA GEMM over interleaved K3 --------------------------
// C[M,N] = A3[M,K3] @ B3[N,K3]^T + bias.  M%128==0, N%256==0, K3%64==0.
// mode bits: 1 = write fp32 C, 2 = write bf16x3 C3 (A-pattern), 4 = relu
#define NSTG  4
#define STGB  49152                 // A 16KB + B 32KB
#define GSMEM (NSTG * STGB)         // 196608

__global__ __launch_bounds__(512, 1)
void gemm_bf16(const __nv_bfloat16* __restrict__ A3, const __nv_bfloat16* __restrict__ B3,
               const float* __restrict__ bias, float* __restrict__ C,
               __nv_bfloat16* __restrict__ C3,
               int M, int N, int K3, int mode)
{
    extern __shared__ char smem[];
    const uint32_t sb = smem_to_u32(smem);
    const int tid  = threadIdx.x;
    const int wid  = tid >> 5;
    const int lane = tid & 31;
    const int warp_m = wid >> 2;        // 0..3 -> 32-row block
    const int warp_n = wid & 3;         // 0..3 -> 64-col block
    const int tile_m = blockIdx.y * 128;
    const int tile_n = blockIdx.x * 256;
    const int NC = K3 >> 6;

    // cp.async addressing
    const int ra = tid >> 3;            // 0..63
    const int ca = tid & 7;
    const __nv_bfloat16* gA = A3 + (size_t)(tile_m + ra) * K3 + ca * 8;
    const __nv_bfloat16* gB = B3 + (size_t)(tile_n + ra) * K3 + ca * 8;
    const uint32_t dA = (uint32_t)(ra * 128 + ((ca ^ (ra & 7)) << 4));

    float acc[2][8][4];
#pragma unroll
    for (int i = 0; i < 2; i++)
#pragma unroll
        for (int j = 0; j < 8; j++)
#pragma unroll
            for (int k = 0; k < 4; k++) acc[i][j][k] = 0.f;

    auto issue = [&](int stage, int chunk) {
        uint32_t s = sb + stage * STGB;
        size_t ko = (size_t)chunk * 64;
        cp_async16(s + dA,        gA + ko);
        cp_async16(s + dA + 8192, gA + ko + (size_t)64 * K3);
#pragma unroll
        for (int i = 0; i < 4; i++)
            cp_async16(s + 16384 + i * 8192 + dA, gB + ko + (size_t)(64 * i) * K3);
        cp_commit();
    };

    // prologue: 3 chunks in flight
    issue(0, 0);
    if (1 < NC) issue(1, 1); else cp_commit();
    if (2 < NC) issue(2, 2); else cp_commit();

    const int l16 = lane & 15;
    const int g   = lane >> 3;           // 0..3 for B x4 groups

    for (int c = 0; c < NC; c++) {
        cp_wait2();
        __syncthreads();
        if (c + 3 < NC) issue((c + 3) & 3, c + 3); else cp_commit();

        uint32_t sA = sb + (c & 3) * STGB;
        uint32_t sB = sA + 16384;
#pragma unroll
        for (int ks = 0; ks < 4; ks++) {
            uint32_t a[2][4];
#pragma unroll
            for (int mt = 0; mt < 2; mt++) {
                int r = warp_m * 32 + mt * 16 + l16;
                uint32_t ku = (uint32_t)((ks * 2 + (lane >> 4)) ^ (r & 7));
                ldmx4(a[mt], sA + (uint32_t)r * 128 + (ku << 4));
            }
            uint32_t b[4][4];
#pragma unroll
            for (int p = 0; p < 4; p++) {
                int rn = warp_n * 64 + p * 16 + (g >> 1) * 8 + (lane & 7);
                uint32_t ku = (uint32_t)((ks * 2 + (g & 1)) ^ (rn & 7));
                ldmx4(b[p], sB + (uint32_t)rn * 128 + (ku << 4));
            }
#pragma unroll
            for (int mt = 0; mt < 2; mt++)
#pragma unroll
                for (int p = 0; p < 4; p++) {
                    mma16816(acc[mt][2 * p],     a[mt], b[p][0], b[p][1]);
                    mma16816(acc[mt][2 * p + 1], a[mt], b[p][2], b[p][3]);
                }
        }
        __syncthreads();
    }

    // epilogue
    const int r0    = lane >> 2;
    const int cpair = (lane & 3) * 2;
#pragma unroll
    for (int mt = 0; mt < 2; mt++) {
#pragma unroll
        for (int nt = 0; nt < 8; nt++) {
            int n  = tile_n + warp_n * 64 + nt * 8 + cpair;
            int m0 = tile_m + warp_m * 32 + mt * 16 + r0;
            float2 bv = *(const float2*)(bias + n);
            float v[2][2];
            v[0][0] = acc[mt][nt][0] + bv.x; v[0][1] = acc[mt][nt][1] + bv.y;
            v[1][0] = acc[mt][nt][2] + bv.x; v[1][1] = acc[mt][nt][3] + bv.y;
            if (mode & 4) {
#pragma unroll
                for (int i = 0; i < 2; i++) {
                    v[i][0] = fmaxf(v[i][0], 0.f); v[i][1] = fmaxf(v[i][1], 0.f);
                }
            }
            if (mode & 1) {
                *(float2*)(C + (size_t)m0 * N + n)       = make_float2(v[0][0], v[0][1]);
                *(float2*)(C + (size_t)(m0 + 8) * N + n) = make_float2(v[1][0], v[1][1]);
            }
            if (mode & 2) {
#pragma unroll
                for (int i = 0; i < 2; i++) {
                    int m = m0 + i * 8;
                    __nv_bfloat16 h0, l0, h1, l1;
                    split1(v[i][0], h0, l0);
                    split1(v[i][1], h1, l1);
                    uint32_t* o = reinterpret_cast<uint32_t*>(C3)
                                + ((3 * ((size_t)m * N + n)) >> 1);
                    o[0] = pack_bf16x2(h0, h0);
                    o[1] = pack_bf16x2(l0, h1);
                    o[2] = pack_bf16x2(h1, l1);
                }
            }
        }
    }
}

// ---------------- fp32 SGEMM (output head: N=64) ------------------------------
#define BM 128
#define BN 128
#define BK 16
#define TM 8
#define TN 8

__global__ __launch_bounds__(256, 2)
void sgemm_bias(const float* __restrict__ A, const float* __restrict__ W,
                const float* __restrict__ bias, float* __restrict__ C,
                int M, int N, int K, int relu)
{
    __shared__ float As[BK][BM + 4];
    __shared__ float Bs[BK][BN + 4];

    const int bm  = blockIdx.y * BM;
    const int bn  = blockIdx.x * BN;
    const int tid = threadIdx.x;
    const int tx  = tid & 15;
    const int ty  = tid >> 4;

    float acc[TM][TN];
#pragma unroll
    for (int i = 0; i < TM; i++)
#pragma unroll
        for (int j = 0; j < TN; j++) acc[i][j] = 0.0f;

    for (int k0 = 0; k0 < K; k0 += BK) {
#pragma unroll
        for (int it = 0; it < 2; it++) {
            int idx = tid + it * 256;
            int row = idx >> 2;
            int c4  = (idx & 3) << 2;
            float4 v = *(const float4*)(A + (size_t)(bm + row) * K + k0 + c4);
            As[c4 + 0][row] = v.x; As[c4 + 1][row] = v.y;
            As[c4 + 2][row] = v.z; As[c4 + 3][row] = v.w;
        }
#pragma unroll
        for (int it = 0; it < 2; it++) {
            int idx = tid + it * 256;
            int row = idx >> 2;
            int c4  = (idx & 3) << 2;
            float4 v = make_float4(0.f, 0.f, 0.f, 0.f);
            if (bn + row < N)
                v = *(const float4*)(W + (size_t)(bn + row) * K + k0 + c4);
            Bs[c4 + 0][row] = v.x; Bs[c4 + 1][row] = v.y;
            Bs[c4 + 2][row] = v.z; Bs[c4 + 3][row] = v.w;
        }
        __syncthreads();

#pragma unroll
        for (int k = 0; k < BK; k++) {
            float a[TM], b[TN];
            float4 t0 = *(const float4*)&As[k][ty * TM];
            float4 t1 = *(const float4*)&As[k][ty * TM + 4];
            a[0]=t0.x; a[1]=t0.y; a[2]=t0.z; a[3]=t0.w;
            a[4]=t1.x; a[5]=t1.y; a[6]=t1.z; a[7]=t1.w;
            float4 u0 = *(const float4*)&Bs[k][tx * TN];
            float4 u1 = *(const float4*)&Bs[k][tx * TN + 4];
            b[0]=u0.x; b[1]=u0.y; b[2]=u0.z; b[3]=u0.w;
            b[4]=u1.x; b[5]=u1.y; b[6]=u1.z; b[7]=u1.w;
#pragma unroll
            for (int i = 0; i < TM; i++)
#pragma unroll
                for (int j = 0; j < TN; j++)
                    acc[i][j] = fmaf(a[i], b[j], acc[i][j]);
        }
        __syncthreads();
    }

#pragma unroll
    for (int i = 0; i < TM; i++) {
        int m = bm + ty * TM + i;
#pragma unroll
        for (int j4 = 0; j4 < 2; j4++) {
            int n = bn + tx * TN + j4 * 4;
            if (n < N) {
                float4 bv = *(const float4*)(bias + n);
                float4 o;
                o.x = acc[i][j4 * 4 + 0] + bv.x;
                o.y = acc[i][j4 * 4 + 1] + bv.y;
                o.z = acc[i][j4 * 4 + 2] + bv.z;
                o.w = acc[i][j4 * 4 + 3] + bv.w;
                if (relu) {
                    o.x = fmaxf(o.x, 0.f); o.y = fmaxf(o.y, 0.f);
                    o.z = fmaxf(o.z, 0.f); o.w = fmaxf(o.w, 0.f);
                }
                *(float4*)(C + (size_t)m * N + n) = o;
            }
        }
    }
}

// ---------------- banded attention (writes bf16x3 ctx directly) ----------------
__global__ __launch_bounds__(256)
void attn_kernel(const float* __restrict__ qkv, __nv_bfloat16* __restrict__ ctx3)
{
    int w    = (blockIdx.x * blockDim.x + threadIdx.x) >> 5;
    int lane = threadIdx.x & 31;
    if (w >= TOK * NHEAD) return;
    int t = w >> 2;
    int h = w & 3;
    int s = t / B_;
    int b = t - s * B_;

    // each lane owns 8 contiguous elements of this head's 256-dim slice
    const float* qp = qkv + (size_t)t * (3 * H_) + h * DH + lane * 8;
    float4 q0 = *(const float4*)(qp);
    float4 q1 = *(const float4*)(qp + 4);

    int lo  = s - WIN; if (lo < 0) lo = 0;
    int cnt = s - lo + 1;

    float sc[WIN + 1];
#pragma unroll
    for (int j = 0; j <= WIN; j++) {
        sc[j] = -1e30f;
        if (j < cnt) {
            int tj = (lo + j) * B_ + b;
            const float* kp = qkv + (size_t)tj * (3 * H_) + H_ + h * DH + lane * 8;
            float4 k0 = *(const float4*)(kp);
            float4 k1 = *(const float4*)(kp + 4);
            float p = q0.x * k0.x + q0.y * k0.y + q0.z * k0.z + q0.w * k0.w
                    + q1.x * k1.x + q1.y * k1.y + q1.z * k1.z + q1.w * k1.w;
#pragma unroll
            for (int o = 16; o; o >>= 1) p += __shfl_xor_sync(0xFFFFFFFFu, p, o);
            sc[j] = p * 0.0625f;   // 1/sqrt(256)
        }
    }
    float m = sc[0];
#pragma unroll
    for (int j = 1; j <= WIN; j++) m = fmaxf(m, sc[j]);
    float e[WIN + 1];
    float se = 0.f;
#pragma unroll
    for (int j = 0; j <= WIN; j++) {
        e[j] = (j < cnt) ? __expf(sc[j] - m) : 0.f;
        se += e[j];
    }
    float inv = 1.f / se;

    float cx[8];
#pragma unroll
    for (int i = 0; i < 8; i++) cx[i] = 0.f;
    for (int j = 0; j < cnt; j++) {
        int tj = (lo + j) * B_ + b;
        const float* vp = qkv + (size_t)tj * (3 * H_) + 2 * H_ + h * DH + lane * 8;
        float4 v0 = *(const float4*)(vp);
        float4 v1 = *(const float4*)(vp + 4);
        float a = e[j] * inv;
        cx[0] = fmaf(a, v0.x, cx[0]); cx[1] = fmaf(a, v0.y, cx[1]);
        cx[2] = fmaf(a, v0.z, cx[2]); cx[3] = fmaf(a, v0.w, cx[3]);
        cx[4] = fmaf(a, v1.x, cx[4]); cx[5] = fmaf(a, v1.y, cx[5]);
        cx[6] = fmaf(a, v1.z, cx[6]); cx[7] = fmaf(a, v1.w, cx[7]);
    }

    // write bf16x3 interleaved (A-pattern), 12 words
    size_t e0 = (size_t)t * H_ + h * DH + lane * 8;
    uint32_t* o = reinterpret_cast<uint32_t*>(ctx3) + ((3 * e0) >> 1);
    uint32_t wbuf[12];
#pragma unroll
    for (int p = 0; p < 4; p++) {
        __nv_bfloat16 h0, l0, h1, l1;
        split1(cx[2 * p], h0, l0);
        split1(cx[2 * p + 1], h1, l1);
        wbuf[3 * p + 0] = pack_bf16x2(h0, h0);
        wbuf[3 * p + 1] = pack_bf16x2(l0, h1);
        wbuf[3 * p + 2] = pack_bf16x2(h1, l1);
    }
#pragma unroll
    for (int p = 0; p < 3; p++)
        *(uint4*)(o + 4 * p) = *(uint4*)(wbuf + 4 * p);
}

// ---------------- residual + LayerNorm (dual write: fp32 + bf16x3) ------------
__device__ __forceinline__ float block_sum(float v, float* red)
{
#pragma unroll
    for (int o = 16; o; o >>= 1) v += __shfl_xor_sync(0xFFFFFFFFu, v, o);
    int wid = threadIdx.x >> 5, lane = threadIdx.x & 31;
    if (lane == 0) red[wid] = v;
    __syncthreads();
    if (threadIdx.x < 32) {
        float r = (threadIdx.x < 8) ? red[threadIdx.x] : 0.f;
#pragma unroll
        for (int o = 4; o; o >>= 1) r += __shfl_xor_sync(0xFFFFFFFFu, r, o);
        if (threadIdx.x == 0) red[0] = r;
    }
    __syncthreads();
    float r = red[0];
    __syncthreads();
    return r;
}

__global__ __launch_bounds__(256)
void resid_ln_kernel(float* __restrict__ x, const float* __restrict__ delta,
                     const float* __restrict__ scale, const float* __restrict__ bias,
                     __nv_bfloat16* __restrict__ x3)
{
    __shared__ float red[8];
    int t   = blockIdx.x;
    int tid = threadIdx.x;
    size_t base = (size_t)t * H_ + tid * 4;

    float4 v = *(const float4*)(x + base);
    float4 d = *(const float4*)(delta + base);
    v.x += d.x; v.y += d.y; v.z += d.z; v.w += d.w;

    float s = v.x + v.y + v.z + v.w;
    float mean = block_sum(s, red) * (1.0f / H_);

    float dx = v.x - mean, dy = v.y - mean, dz = v.z - mean, dw = v.w - mean;
    float sq = dx * dx + dy * dy + dz * dz + dw * dw;
    float var = block_sum(sq, red) * (1.0f / H_);
    float rstd = rsqrtf(var + EPS);

    float4 sc = *(const float4*)(scale + tid * 4);
    float4 bi = *(const float4*)(bias + tid * 4);
    float4 o;
    o.x = dx * rstd * sc.x + bi.x;
    o.y = dy * rstd * sc.y + bi.y;
    o.z = dz * rstd * sc.z + bi.z;
    o.w = dw * rstd * sc.w + bi.w;
    *(float4*)(x + base) = o;

    __nv_bfloat16 h0, l0, h1, l1, h2, l2, h3, l3;
    split1(o.x, h0, l0); split1(o.y, h1, l1);
    split1(o.z, h2, l2); split1(o.w, h3, l3);
    uint32_t* o3 = reinterpret_cast<uint32_t*>(x3) + (size_t)t * (3 * H_ / 2) + tid * 6;
    o3[0] = pack_bf16x2(h0, h0); o3[1] = pack_bf16x2(l0, h1); o3[2] = pack_bf16x2(h1, l1);
    o3[3] = pack_bf16x2(h2, h2); o3[4] = pack_bf16x2(l2, h3); o3[5] = pack_bf16x2(h3, l3);
}

// ---------------- host orchestration ------------------------------------------
static inline void run_conv(const float* in, __nv_bfloat16* out, size_t nelem, int pattern)
{
    int npairs = (int)(nelem / 2);
    conv_split<<<(npairs + 255) / 256, 256>>>(in, out, npairs, pattern);
}

static inline void run_gemm_bf16(const __nv_bfloat16* A3, const __nv_bfloat16* B3,
                                 const float* bias, float* C, __nv_bfloat16* C3,
                                 int M, int N, int K3, int mode)
{
    static int attr_set = 0;
    if (!attr_set) {
        cudaFuncSetAttribute(gemm_bf16, cudaFuncAttributeMaxDynamicSharedMemorySize, GSMEM);
        attr_set = 1;
    }
    dim3 grid(N / 256, M / 128);
    gemm_bf16<<<grid, 512, GSMEM>>>(A3, B3, bias, C, C3, M, N, K3, mode);
}

extern "C" void kernel_launch(void* const* d_in, const int* in_sizes, int n_in,
                              void* d_out, int out_size)
{
    const float* src   = (const float*)d_in[0];
    const float* Wenc  = (const float*)d_in[1];
    const float* benc  = (const float*)d_in[2];
    const float* Wqkv  = (const float*)d_in[3];
    const float* bqkv  = (const float*)d_in[4];
    const float* Wo    = (const float*)d_in[5];
    const float* bo    = (const float*)d_in[6];
    const float* W1    = (const float*)d_in[7];
    const float* b1    = (const float*)d_in[8];
    const float* W2    = (const float*)d_in[9];
    const float* b2    = (const float*)d_in[10];
    const float* ln1_s = (const float*)d_in[11];
    const float* ln1_b = (const float*)d_in[12];
    const float* ln2_s = (const float*)d_in[13];
    const float* ln2_b = (const float*)d_in[14];
    const float* Wout  = (const float*)d_in[15];
    const float* bout  = (const float*)d_in[16];
    float* out = (float*)d_out;

    float *x, *qkv, *tmp;
    __nv_bfloat16 *src3, *x3, *ctx3, *h13, *wenc3, *wqkv3, *wo3, *w13, *w23;
    cudaGetSymbolAddress((void**)&x,    g_x);
    cudaGetSymbolAddress((void**)&qkv,  g_qkv);
    cudaGetSymbolAddress((void**)&tmp,  g_tmp);
    cudaGetSymbolAddress((void**)&src3, g_src3);
    cudaGetSymbolAddress((void**)&x3,   g_x3);
    cudaGetSymbolAddress((void**)&ctx3, g_ctx3);
    cudaGetSymbolAddress((void**)&h13,  g_h13);
    cudaGetSymbolAddress((void**)&wenc3, g_wenc3);
    cudaGetSymbolAddress((void**)&wqkv3, g_wqkv3);
    cudaGetSymbolAddress((void**)&wo3,   g_wo3);
    cudaGetSymbolAddress((void**)&w13,   g_w13);
    cudaGetSymbolAddress((void**)&w23,   g_w23);

    // launch 0,1: src + encoder weight conversion
    run_conv(src,  src3,  (size_t)TOK * INDIM, 0);
    run_conv(Wenc, wenc3, (size_t)H_ * INDIM, 1);
    // launch 2: encoder GEMM (x + x3)
    run_gemm_bf16(src3, wenc3, benc, x, x3, TOK, H_, K3IN, 1 | 2);
    // launch 3: Wqkv conversion (all layers)
    run_conv(Wqkv, wqkv3, (size_t)L_ * 3 * H_ * H_, 1);
    // launch 4: Wo/W1/W2 conversion combined
    {
        int npairs = (int)((size_t)L_ * H_ * H_ / 2);
        dim3 grid((npairs + 255) / 256, 3);
        conv_split3<<<grid, 256>>>(Wo, W1, W2, wo3, w13, w23, npairs);
    }

    for (int l = 0; l < L_; l++) {
        const __nv_bfloat16* wqkv3_l = wqkv3 + (size_t)l * 3 * H_ * K3H;
        const __nv_bfloat16* wo3_l   = wo3   + (size_t)l * H_ * K3H;
        const __nv_bfloat16* w13_l   = w13   + (size_t)l * DFF_ * K3H;
        const __nv_bfloat16* w23_l   = w23   + (size_t)l * H_ * K3H;
        const float* bqkv_l = bqkv + (size_t)l * 3 * H_;
        const float* bo_l   = bo   + (size_t)l * H_;
        const float* b1_l   = b1   + (size_t)l * DFF_;
        const float* b2_l   = b2   + (size_t)l * H_;

        // launch 5 (layer 0): QKV GEMM -> profiled by ncu -s 5
        run_gemm_bf16(x3, wqkv3_l, bqkv_l, qkv, nullptr, TOK, 3 * H_, K3H, 1);
        // banded attention -> bf16x3 ctx directly
        attn_kernel<<<(TOK * NHEAD) / 8, 256>>>(qkv, ctx3);
        // attn_out = ctx @ Wo^T + bo
        run_gemm_bf16(ctx3, wo3_l, bo_l, tmp, nullptr, TOK, H_, K3H, 1);
        // x = LN(x + attn_out), dual write x3
        resid_ln_kernel<<<TOK, 256>>>(x, tmp, ln1_s + (size_t)l * H_, ln1_b + (size_t)l * H_, x3);
        // h1 = relu(x @ W1^T + b1) -> bf16x3 only
        run_gemm_bf16(x3, w13_l, b1_l, nullptr, h13, TOK, DFF_, K3H, 2 | 4);
        // ff = h1 @ W2^T + b2
        run_gemm_bf16(h13, w23_l, b2_l, tmp, nullptr, TOK, H_, K3H, 1);
        // x = LN(x + ff), dual write x3
        resid_ln_kernel<<<TOK, 256>>>(x, tmp, ln2_s + (size_t)l * H_, ln2_b + (size_t)l * H_, x3);
    }

    // out = x @ Wout^T + bout   (N=64 -> fp32 path)
    dim3 grid((OUTD + BN - 1) / BN, TOK / BM);
    sgemm_bias<<<grid, 256>>>(x, Wout, bout, out, TOK, OUTD, H_, 0);
}

// round 11
// speedup vs baseline: 3.7683x; 1.4891x over previous
#include <cuda_runtime.h>
#include <cuda_fp16.h>
#include <cstdint>
#include <cstddef>

#define S_    2048
#define B_    4
#define INDIM 64
#define H_    1024
#define DFF_  1024
#define OUTD  64
#define L_    3
#define NHEAD 4
#define DH    (H_ / NHEAD)   // 256
#define WIN   4
#define TOK   (S_ * B_)      // 8192
#define EPS   1e-5f
#define K2H   (2 * H_)       // 2048
#define K2IN  (2 * INDIM)    // 128
#define NPADH 256            // padded head N

// ---------------- scratch (static device globals) -----------------------------
__device__ float g_x[TOK * H_];
__device__ float g_qkv[TOK * 3 * H_];
__device__ float g_tmp[TOK * H_];
__device__ float g_bout_pad[NPADH];

__device__ __align__(256) __half g_src2[TOK * K2IN];
__device__ __align__(256) __half g_x2[TOK * K2H];
__device__ __align__(256) __half g_ctx2[TOK * K2H];
__device__ __align__(256) __half g_h12[TOK * K2H];
__device__ __align__(256) __half g_wenc2[H_ * K2IN];
__device__ __align__(256) __half g_wqkv2[L_ * 3 * H_ * K2H];
__device__ __align__(256) __half g_wo2[L_ * H_ * K2H];
__device__ __align__(256) __half g_w12[L_ * DFF_ * K2H];
__device__ __align__(256) __half g_w22[L_ * H_ * K2H];
__device__ __align__(256) __half g_wout2[NPADH * K2H];

// ---------------- helpers -----------------------------------------------------
__device__ __forceinline__ uint32_t smem_to_u32(const void* p) {
    uint32_t a;
    asm("{ .reg .u64 t; cvta.to.shared.u64 t, %1; cvt.u32.u64 %0, t; }"
        : "=r"(a) : "l"(p));
    return a;
}
__device__ __forceinline__ uint32_t pack_h2(__half a, __half b) {
    __half2 t = __halves2half2(a, b);
    return *reinterpret_cast<uint32_t*>(&t);
}
__device__ __forceinline__ void split1(float v, __half& h, __half& l) {
    h = __float2half(v);
    l = __float2half(v - __half2float(h));
}
__device__ __forceinline__ void cp_async16(uint32_t dst, const void* src) {
    asm volatile("cp.async.cg.shared.global [%0], [%1], 16;"
                 :: "r"(dst), "l"(src) : "memory");
}
__device__ __forceinline__ void cp_commit() {
    asm volatile("cp.async.commit_group;" ::: "memory");
}
__device__ __forceinline__ void cp_wait2() {
    asm volatile("cp.async.wait_group 2;" ::: "memory");
}
__device__ __forceinline__ void ldmx4(uint32_t* r, uint32_t a) {
    asm volatile("ldmatrix.sync.aligned.m8n8.x4.shared.b16 {%0,%1,%2,%3}, [%4];"
                 : "=r"(r[0]), "=r"(r[1]), "=r"(r[2]), "=r"(r[3]) : "r"(a));
}
__device__ __forceinline__ void mma16816(float* d, const uint32_t* a,
                                         uint32_t b0, uint32_t b1) {
    asm volatile("mma.sync.aligned.m16n8k16.row.col.f32.f16.f16.f32 "
                 "{%0,%1,%2,%3}, {%4,%5,%6,%7}, {%8,%9}, {%0,%1,%2,%3};"
                 : "+f"(d[0]), "+f"(d[1]), "+f"(d[2]), "+f"(d[3])
                 : "r"(a[0]), "r"(a[1]), "r"(a[2]), "r"(a[3]), "r"(b0), "r"(b1));
}

// ---------------- conversion: fp32 -> interleaved fp16x2 ----------------------
// pattern 0 (A side): per k -> [hi, lo]; pattern 1 (B side): [hi, hi]
__device__ __forceinline__ void conv_pair(const float* in, uint32_t* o, int pattern) {
    float f0 = in[0], f1 = in[1];
    __half h0, l0, h1, l1;
    split1(f0, h0, l0);
    split1(f1, h1, l1);
    if (pattern == 0) {
        o[0] = pack_h2(h0, l0); o[1] = pack_h2(h1, l1);
    } else {
        o[0] = pack_h2(h0, h0); o[1] = pack_h2(h1, h1);
    }
}

__global__ void conv_split(const float* __restrict__ in, __half* __restrict__ out,
                           int npairs, int pattern)
{
    int i = blockIdx.x * blockDim.x + threadIdx.x;
    if (i >= npairs) return;
    conv_pair(in + 2 * (size_t)i, reinterpret_cast<uint32_t*>(out) + 2 * (size_t)i, pattern);
}

__global__ void conv_split3(const float* __restrict__ a, const float* __restrict__ b,
                            const float* __restrict__ c,
                            __half* __restrict__ oa, __half* __restrict__ ob,
                            __half* __restrict__ oc, int npairs)
{
    int i = blockIdx.x * blockDim.x + threadIdx.x;
    if (i >= npairs) return;
    const float* in = (blockIdx.y == 0) ? a : (blockIdx.y == 1) ? b : c;
    __half* out = (blockIdx.y == 0) ? oa : (blockIdx.y == 1) ? ob : oc;
    conv_pair(in + 2 * (size_t)i, reinterpret_cast<uint32_t*>(out) + 2 * (size_t)i, 1);
}

// Wout [OUTD, H_] -> padded [NPADH, K2H] (zero rows beyond OUTD), pattern B.
__global__ void conv_wout(const float* __restrict__ W, __half* __restrict__ out, int npairs)
{
    int i = blockIdx.x * blockDim.x + threadIdx.x;
    if (i >= npairs) return;
    uint32_t* o = reinterpret_cast<uint32_t*>(out) + 2 * (size_t)i;
    size_t e = 2 * (size_t)i;
    if (e < (size_t)OUTD * H_) {
        conv_pair(W + e, o, 1);
    } else {
        o[0] = 0; o[1] = 0;
    }
}

__global__ void pad_bias(const float* __restrict__ b, float* __restrict__ o)
{
    int i = threadIdx.x;
    o[i] = (i < OUTD) ? b[i] : 0.f;
}

// ---------------- fp16 HMMA GEMM over interleaved K2 --------------------------
// C[M,Nout] = A2[M,K2] @ B2[N,K2]^T + bias.  M%128==0, N%256==0, K2%64==0.
// mode bits: 1 = write fp32 C (cols < Nout), 2 = write fp16x2 C2 (A-pattern), 4 = relu
#define NSTG  4
#define STGB  49152                 // A 16KB + B 32KB
#define GSMEM (NSTG * STGB)         // 196608

__global__ __launch_bounds__(512, 1)
void gemm_fp16(const __half* __restrict__ A2, const __half* __restrict__ B2,
               const float* __restrict__ bias, float* __restrict__ C,
               __half* __restrict__ C2,
               int M, int N, int K2, int Nout, int mode)
{
    extern __shared__ char smem[];
    const uint32_t sb = smem_to_u32(smem);
    const int tid  = threadIdx.x;
    const int wid  = tid >> 5;
    const int lane = tid & 31;
    const int warp_m = wid >> 2;        // 0..3 -> 32-row block
    const int warp_n = wid & 3;         // 0..3 -> 64-col block
    const int tile_m = blockIdx.y * 128;
    const int tile_n = blockIdx.x * 256;
    const int NC = K2 >> 6;

    const int ra = tid >> 3;            // 0..63
    const int ca = tid & 7;
    const __half* gA = A2 + (size_t)(tile_m + ra) * K2 + ca * 8;
    const __half* gB = B2 + (size_t)(tile_n + ra) * K2 + ca * 8;
    const uint32_t dA = (uint32_t)(ra * 128 + ((ca ^ (ra & 7)) << 4));

    float acc[2][8][4];
#pragma unroll
    for (int i = 0; i < 2; i++)
#pragma unroll
        for (int j = 0; j < 8; j++)
#pragma unroll
            for (int k = 0; k < 4; k++) acc[i][j][k] = 0.f;

    auto issue = [&](int stage, int chunk) {
        uint32_t s = sb + stage * STGB;
        size_t ko = (size_t)chunk * 64;
        cp_async16(s + dA,        gA + ko);
        cp_async16(s + dA + 8192, gA + ko + (size_t)64 * K2);
#pragma unroll
        for (int i = 0; i < 4; i++)
            cp_async16(s + 16384 + i * 8192 + dA, gB + ko + (size_t)(64 * i) * K2);
        cp_commit();
    };

    issue(0, 0);
    if (1 < NC) issue(1, 1); else cp_commit();
    if (2 < NC) issue(2, 2); else cp_commit();

    const int l16 = lane & 15;
    const int g   = lane >> 3;

    for (int c = 0; c < NC; c++) {
        cp_wait2();
        __syncthreads();
        if (c + 3 < NC) issue((c + 3) & 3, c + 3); else cp_commit();

        uint32_t sA = sb + (c & 3) * STGB;
        uint32_t sB = sA + 16384;
#pragma unroll
        for (int ks = 0; ks < 4; ks++) {
            uint32_t a[2][4];
#pragma unroll
            for (int mt = 0; mt < 2; mt++) {
                int r = warp_m * 32 + mt * 16 + l16;
                uint32_t ku = (uint32_t)((ks * 2 + (lane >> 4)) ^ (r & 7));
                ldmx4(a[mt], sA + (uint32_t)r * 128 + (ku << 4));
            }
            uint32_t b[4][4];
#pragma unroll
            for (int p = 0; p < 4; p++) {
                int rn = warp_n * 64 + p * 16 + (g >> 1) * 8 + (lane & 7);
                uint32_t ku = (uint32_t)((ks * 2 + (g & 1)) ^ (rn & 7));
                ldmx4(b[p], sB + (uint32_t)rn * 128 + (ku << 4));
            }
#pragma unroll
            for (int mt = 0; mt < 2; mt++)
#pragma unroll
                for (int p = 0; p < 4; p++) {
                    mma16816(acc[mt][2 * p],     a[mt], b[p][0], b[p][1]);
                    mma16816(acc[mt][2 * p + 1], a[mt], b[p][2], b[p][3]);
                }
        }
        __syncthreads();
    }

    // epilogue
    const int r0    = lane >> 2;
    const int cpair = (lane & 3) * 2;
#pragma unroll
    for (int mt = 0; mt < 2; mt++) {
#pragma unroll
        for (int nt = 0; nt < 8; nt++) {
            int n  = tile_n + warp_n * 64 + nt * 8 + cpair;
            int m0 = tile_m + warp_m * 32 + mt * 16 + r0;
            if (n >= Nout) continue;
            float2 bv = *(const float2*)(bias + n);
            float v[2][2];
            v[0][0] = acc[mt][nt][0] + bv.x; v[0][1] = acc[mt][nt][1] + bv.y;
            v[1][0] = acc[mt][nt][2] + bv.x; v[1][1] = acc[mt][nt][3] + bv.y;
            if (mode & 4) {
#pragma unroll
                for (int i = 0; i < 2; i++) {
                    v[i][0] = fmaxf(v[i][0], 0.f); v[i][1] = fmaxf(v[i][1], 0.f);
                }
            }
            if (mode & 1) {
                *(float2*)(C + (size_t)m0 * Nout + n)       = make_float2(v[0][0], v[0][1]);
                *(float2*)(C + (size_t)(m0 + 8) * Nout + n) = make_float2(v[1][0], v[1][1]);
            }
            if (mode & 2) {
#pragma unroll
                for (int i = 0; i < 2; i++) {
                    int m = m0 + i * 8;
                    __half h0, l0, h1, l1;
                    split1(v[i][0], h0, l0);
                    split1(v[i][1], h1, l1);
                    uint2 w;
                    w.x = pack_h2(h0, l0);
                    w.y = pack_h2(h1, l1);
                    *(uint2*)(reinterpret_cast<uint32_t*>(C2) + (size_t)m * Nout + n) = w;
                }
            }
        }
    }
}

// ---------------- banded attention (writes fp16x2 ctx directly) ----------------
__global__ __launch_bounds__(256)
void attn_kernel(const float* __restrict__ qkv, __half* __restrict__ ctx2)
{
    int w    = (blockIdx.x * blockDim.x + threadIdx.x) >> 5;
    int lane = threadIdx.x & 31;
    if (w >= TOK * NHEAD) return;
    int t = w >> 2;
    int h = w & 3;
    int s = t / B_;
    int b = t - s * B_;

    const float* qp = qkv + (size_t)t * (3 * H_) + h * DH + lane * 8;
    float4 q0 = *(const float4*)(qp);
    float4 q1 = *(const float4*)(qp + 4);

    int lo  = s - WIN; if (lo < 0) lo = 0;
    int cnt = s - lo + 1;

    float sc[WIN + 1];
#pragma unroll
    for (int j = 0; j <= WIN; j++) {
        sc[j] = -1e30f;
        if (j < cnt) {
            int tj = (lo + j) * B_ + b;
            const float* kp = qkv + (size_t)tj * (3 * H_) + H_ + h * DH + lane * 8;
            float4 k0 = *(const float4*)(kp);
            float4 k1 = *(const float4*)(kp + 4);
            float p = q0.x * k0.x + q0.y * k0.y + q0.z * k0.z + q0.w * k0.w
                    + q1.x * k1.x + q1.y * k1.y + q1.z * k1.z + q1.w * k1.w;
#pragma unroll
            for (int o = 16; o; o >>= 1) p += __shfl_xor_sync(0xFFFFFFFFu, p, o);
            sc[j] = p * 0.0625f;
        }
    }
    float m = sc[0];
#pragma unroll
    for (int j = 1; j <= WIN; j++) m = fmaxf(m, sc[j]);
    float e[WIN + 1];
    float se = 0.f;
#pragma unroll
    for (int j = 0; j <= WIN; j++) {
        e[j] = (j < cnt) ? __expf(sc[j] - m) : 0.f;
        se += e[j];
    }
    float inv = 1.f / se;

    float cx[8];
#pragma unroll
    for (int i = 0; i < 8; i++) cx[i] = 0.f;
    for (int j = 0; j < cnt; j++) {
        int tj = (lo + j) * B_ + b;
        const float* vp = qkv + (size_t)tj * (3 * H_) + 2 * H_ + h * DH + lane * 8;
        float4 v0 = *(const float4*)(vp);
        float4 v1 = *(const float4*)(vp + 4);
        float a = e[j] * inv;
        cx[0] = fmaf(a, v0.x, cx[0]); cx[1] = fmaf(a, v0.y, cx[1]);
        cx[2] = fmaf(a, v0.z, cx[2]); cx[3] = fmaf(a, v0.w, cx[3]);
        cx[4] = fmaf(a, v1.x, cx[4]); cx[5] = fmaf(a, v1.y, cx[5]);
        cx[6] = fmaf(a, v1.z, cx[6]); cx[7] = fmaf(a, v1.w, cx[7]);
    }

    // fp16x2 A-pattern: 1 word per element, 8 words
    size_t e0 = (size_t)t * H_ + h * DH + lane * 8;
    uint32_t* o = reinterpret_cast<uint32_t*>(ctx2) + e0;
    uint32_t wbuf[8];
#pragma unroll
    for (int p = 0; p < 8; p++) {
        __half hh, ll;
        split1(cx[p], hh, ll);
        wbuf[p] = pack_h2(hh, ll);
    }
    *(uint4*)(o)     = *(uint4*)(wbuf);
    *(uint4*)(o + 4) = *(uint4*)(wbuf + 4);
}

// ---------------- residual + LayerNorm (dual write: fp32 + fp16x2) ------------
__device__ __forceinline__ float block_sum(float v, float* red)
{
#pragma unroll
    for (int o = 16; o; o >>= 1) v += __shfl_xor_sync(0xFFFFFFFFu, v, o);
    int wid = threadIdx.x >> 5, lane = threadIdx.x & 31;
    if (lane == 0) red[wid] = v;
    __syncthreads();
    if (threadIdx.x < 32) {
        float r = (threadIdx.x < 8) ? red[threadIdx.x] : 0.f;
#pragma unroll
        for (int o = 4; o; o >>= 1) r += __shfl_xor_sync(0xFFFFFFFFu, r, o);
        if (threadIdx.x == 0) red[0] = r;
    }
    __syncthreads();
    float r = red[0];
    __syncthreads();
    return r;
}

__global__ __launch_bounds__(256)
void resid_ln_kernel(float* __restrict__ x, const float* __restrict__ delta,
                     const float* __restrict__ scale, const float* __restrict__ bias,
                     __half* __restrict__ x2)
{
    __shared__ float red[8];
    int t   = blockIdx.x;
    int tid = threadIdx.x;
    size_t base = (size_t)t * H_ + tid * 4;

    float4 v = *(const float4*)(x + base);
    float4 d = *(const float4*)(delta + base);
    v.x += d.x; v.y += d.y; v.z += d.z; v.w += d.w;

    float s = v.x + v.y + v.z + v.w;
    float mean = block_sum(s, red) * (1.0f / H_);

    float dx = v.x - mean, dy = v.y - mean, dz = v.z - mean, dw = v.w - mean;
    float sq = dx * dx + dy * dy + dz * dz + dw * dw;
    float var = block_sum(sq, red) * (1.0f / H_);
    float rstd = rsqrtf(var + EPS);

    float4 sc = *(const float4*)(scale + tid * 4);
    float4 bi = *(const float4*)(bias + tid * 4);
    float4 o;
    o.x = dx * rstd * sc.x + bi.x;
    o.y = dy * rstd * sc.y + bi.y;
    o.z = dz * rstd * sc.z + bi.z;
    o.w = dw * rstd * sc.w + bi.w;
    *(float4*)(x + base) = o;

    __half h0, l0, h1, l1, h2, l2, h3, l3;
    split1(o.x, h0, l0); split1(o.y, h1, l1);
    split1(o.z, h2, l2); split1(o.w, h3, l3);
    uint32_t wbuf[4];
    wbuf[0] = pack_h2(h0, l0); wbuf[1] = pack_h2(h1, l1);
    wbuf[2] = pack_h2(h2, l2); wbuf[3] = pack_h2(h3, l3);
    *(uint4*)(reinterpret_cast<uint32_t*>(x2) + base) = *(uint4*)wbuf;
}

// ---------------- host orchestration ------------------------------------------
static inline void run_conv(const float* in, __half* out, size_t nelem, int pattern)
{
    int npairs = (int)(nelem / 2);
    conv_split<<<(npairs + 255) / 256, 256>>>(in, out, npairs, pattern);
}

static inline void run_gemm(const __half* A2, const __half* B2,
                            const float* bias, float* C, __half* C2,
                            int M, int N, int K2, int Nout, int mode)
{
    static int attr_set = 0;
    if (!attr_set) {
        cudaFuncSetAttribute(gemm_fp16, cudaFuncAttributeMaxDynamicSharedMemorySize, GSMEM);
        attr_set = 1;
    }
    dim3 grid(N / 256, M / 128);
    gemm_fp16<<<grid, 512, GSMEM>>>(A2, B2, bias, C, C2, M, N, K2, Nout, mode);
}

extern "C" void kernel_launch(void* const* d_in, const int* in_sizes, int n_in,
                              void* d_out, int out_size)
{
    const float* src   = (const float*)d_in[0];
    const float* Wenc  = (const float*)d_in[1];
    const float* benc  = (const float*)d_in[2];
    const float* Wqkv  = (const float*)d_in[3];
    const float* bqkv  = (const float*)d_in[4];
    const float* Wo    = (const float*)d_in[5];
    const float* bo    = (const float*)d_in[6];
    const float* W1    = (const float*)d_in[7];
    const float* b1    = (const float*)d_in[8];
    const float* W2    = (const float*)d_in[9];
    const float* b2    = (const float*)d_in[10];
    const float* ln1_s = (const float*)d_in[11];
    const float* ln1_b = (const float*)d_in[12];
    const float* ln2_s = (const float*)d_in[13];
    const float* ln2_b = (const float*)d_in[14];
    const float* Wout  = (const float*)d_in[15];
    const float* bout  = (const float*)d_in[16];
    float* out = (float*)d_out;

    float *x, *qkv, *tmp, *bout_pad;
    __half *src2, *x2, *ctx2, *h12, *wenc2, *wqkv2, *wo2, *w12, *w22, *wout2;
    cudaGetSymbolAddress((void**)&x,    g_x);
    cudaGetSymbolAddress((void**)&qkv,  g_qkv);
    cudaGetSymbolAddress((void**)&tmp,  g_tmp);
    cudaGetSymbolAddress((void**)&bout_pad, g_bout_pad);
    cudaGetSymbolAddress((void**)&src2, g_src2);
    cudaGetSymbolAddress((void**)&x2,   g_x2);
    cudaGetSymbolAddress((void**)&ctx2, g_ctx2);
    cudaGetSymbolAddress((void**)&h12,  g_h12);
    cudaGetSymbolAddress((void**)&wenc2, g_wenc2);
    cudaGetSymbolAddress((void**)&wqkv2, g_wqkv2);
    cudaGetSymbolAddress((void**)&wo2,   g_wo2);
    cudaGetSymbolAddress((void**)&w12,   g_w12);
    cudaGetSymbolAddress((void**)&w22,   g_w22);
    cudaGetSymbolAddress((void**)&wout2, g_wout2);

    // conversions
    run_conv(src,  src2,  (size_t)TOK * INDIM, 0);
    run_conv(Wenc, wenc2, (size_t)H_ * INDIM, 1);
    // encoder GEMM (x + x2)
    run_gemm(src2, wenc2, benc, x, x2, TOK, H_, K2IN, H_, 1 | 2);
    run_conv(Wqkv, wqkv2, (size_t)L_ * 3 * H_ * H_, 1);
    {
        int npairs = (int)((size_t)L_ * H_ * H_ / 2);
        dim3 grid((npairs + 255) / 256, 3);
        conv_split3<<<grid, 256>>>(Wo, W1, W2, wo2, w12, w22, npairs);
    }
    {
        int npairs = (int)((size_t)NPADH * H_ / 2);
        conv_wout<<<(npairs + 255) / 256, 256>>>(Wout, wout2, npairs);
        pad_bias<<<1, NPADH>>>(bout, bout_pad);
    }

    for (int l = 0; l < L_; l++) {
        const __half* wqkv2_l = wqkv2 + (size_t)l * 3 * H_ * K2H;
        const __half* wo2_l   = wo2   + (size_t)l * H_ * K2H;
        const __half* w12_l   = w12   + (size_t)l * DFF_ * K2H;
        const __half* w22_l   = w22   + (size_t)l * H_ * K2H;
        const float* bqkv_l = bqkv + (size_t)l * 3 * H_;
        const float* bo_l   = bo   + (size_t)l * H_;
        const float* b1_l   = b1   + (size_t)l * DFF_;
        const float* b2_l   = b2   + (size_t)l * H_;

        // qkv = x @ Wqkv^T + bqkv (fp32 out)
        run_gemm(x2, wqkv2_l, bqkv_l, qkv, nullptr, TOK, 3 * H_, K2H, 3 * H_, 1);
        // banded attention -> fp16x2 ctx
        attn_kernel<<<(TOK * NHEAD) / 8, 256>>>(qkv, ctx2);
        // attn_out = ctx @ Wo^T + bo
        run_gemm(ctx2, wo2_l, bo_l, tmp, nullptr, TOK, H_, K2H, H_, 1);
        // x = LN(x + attn_out), dual write x2
        resid_ln_kernel<<<TOK, 256>>>(x, tmp, ln1_s + (size_t)l * H_, ln1_b + (size_t)l * H_, x2);
        // h1 = relu(x @ W1^T + b1) -> fp16x2 only
        run_gemm(x2, w12_l, b1_l, nullptr, h12, TOK, DFF_, K2H, DFF_, 2 | 4);
        // ff = h1 @ W2^T + b2
        run_gemm(h12, w22_l, b2_l, tmp, nullptr, TOK, H_, K2H, H_, 1);
        // x = LN(x + ff), dual write x2
        resid_ln_kernel<<<TOK, 256>>>(x, tmp, ln2_s + (size_t)l * H_, ln2_b + (size_t)l * H_, x2);
    }

    // out = x @ Wout^T + bout  (padded N=256, store masked to 64)
    run_gemm(x2, wout2, bout_pad, out, nullptr, TOK, NPADH, K2H, OUTD, 1);
}

// round 13
// speedup vs baseline: 6.4756x; 1.7184x over previous
#include <cuda_runtime.h>
#include <cuda_fp16.h>
#include <cstdint>
#include <cstddef>

#define S_    2048
#define B_    4
#define INDIM 64
#define H_    1024
#define DFF_  1024
#define OUTD  64
#define L_    3
#define NHEAD 4
#define DH    (H_ / NHEAD)   // 256
#define WIN   4
#define TOK   (S_ * B_)      // 8192
#define EPS   1e-5f
#define NPADH 256            // padded head N

// ---------------- scratch (static device globals) -----------------------------
__device__ float g_x[TOK * H_];
__device__ float g_qkv[TOK * 3 * H_];
__device__ float g_tmp[TOK * H_];
__device__ float g_bout_pad[NPADH];

__device__ __align__(256) __half g_src2[TOK * INDIM];
__device__ __align__(256) __half g_x2[TOK * H_];
__device__ __align__(256) __half g_ctx2[TOK * H_];
__device__ __align__(256) __half g_h12[TOK * H_];
__device__ __align__(256) __half g_wenc2[H_ * INDIM];
__device__ __align__(256) __half g_wqkv2[L_ * 3 * H_ * H_];
__device__ __align__(256) __half g_wo2[L_ * H_ * H_];
__device__ __align__(256) __half g_w12[L_ * DFF_ * H_];
__device__ __align__(256) __half g_w22[L_ * H_ * DFF_];
__device__ __align__(256) __half g_wout2[NPADH * H_];

// ---------------- helpers -----------------------------------------------------
__device__ __forceinline__ uint32_t smem_to_u32(const void* p) {
    uint32_t a;
    asm("{ .reg .u64 t; cvta.to.shared.u64 t, %1; cvt.u32.u64 %0, t; }"
        : "=r"(a) : "l"(p));
    return a;
}
__device__ __forceinline__ uint32_t pack_h2(__half a, __half b) {
    __half2 t = __halves2half2(a, b);
    return *reinterpret_cast<uint32_t*>(&t);
}
__device__ __forceinline__ void cp_async16(uint32_t dst, const void* src) {
    asm volatile("cp.async.cg.shared.global [%0], [%1], 16;"
                 :: "r"(dst), "l"(src) : "memory");
}
__device__ __forceinline__ void cp_commit() {
    asm volatile("cp.async.commit_group;" ::: "memory");
}
__device__ __forceinline__ void cp_wait2() {
    asm volatile("cp.async.wait_group 2;" ::: "memory");
}
__device__ __forceinline__ void ldmx4(uint32_t* r, uint32_t a) {
    asm volatile("ldmatrix.sync.aligned.m8n8.x4.shared.b16 {%0,%1,%2,%3}, [%4];"
                 : "=r"(r[0]), "=r"(r[1]), "=r"(r[2]), "=r"(r[3]) : "r"(a));
}
__device__ __forceinline__ void mma16816(float* d, const uint32_t* a,
                                         uint32_t b0, uint32_t b1) {
    asm volatile("mma.sync.aligned.m16n8k16.row.col.f32.f16.f16.f32 "
                 "{%0,%1,%2,%3}, {%4,%5,%6,%7}, {%8,%9}, {%0,%1,%2,%3};"
                 : "+f"(d[0]), "+f"(d[1]), "+f"(d[2]), "+f"(d[3])
                 : "r"(a[0]), "r"(a[1]), "r"(a[2]), "r"(a[3]), "r"(b0), "r"(b1));
}

// ---------------- conversion: fp32 -> fp16 (quad per thread) -------------------
__device__ __forceinline__ void cast_quad(const float* in, uint32_t* o) {
    float4 v = *(const float4*)in;
    o[0] = pack_h2(__float2half(v.x), __float2half(v.y));
    o[1] = pack_h2(__float2half(v.z), __float2half(v.w));
}

// segment 0: src (nqA quads), segment 1: Wenc
__global__ void conv_seg2(const float* __restrict__ a, const float* __restrict__ b,
                          __half* __restrict__ oa, __half* __restrict__ ob, int nqA, int nqTot)
{
    int i = blockIdx.x * blockDim.x + threadIdx.x;
    if (i >= nqTot) return;
    if (i < nqA) cast_quad(a + 4 * (size_t)i, reinterpret_cast<uint32_t*>(oa) + 2 * (size_t)i);
    else {
        int j = i - nqA;
        cast_quad(b + 4 * (size_t)j, reinterpret_cast<uint32_t*>(ob) + 2 * (size_t)j);
    }
}

__global__ void conv_cast(const float* __restrict__ in, __half* __restrict__ out, int nq)
{
    int i = blockIdx.x * blockDim.x + threadIdx.x;
    if (i >= nq) return;
    cast_quad(in + 4 * (size_t)i, reinterpret_cast<uint32_t*>(out) + 2 * (size_t)i);
}

__global__ void conv_cast3(const float* __restrict__ a, const float* __restrict__ b,
                           const float* __restrict__ c,
                           __half* __restrict__ oa, __half* __restrict__ ob,
                           __half* __restrict__ oc, int nq)
{
    int i = blockIdx.x * blockDim.x + threadIdx.x;
    if (i >= nq) return;
    const float* in = (blockIdx.y == 0) ? a : (blockIdx.y == 1) ? b : c;
    __half* out = (blockIdx.y == 0) ? oa : (blockIdx.y == 1) ? ob : oc;
    cast_quad(in + 4 * (size_t)i, reinterpret_cast<uint32_t*>(out) + 2 * (size_t)i);
}

// Wout [OUTD, H_] -> padded [NPADH, H_] fp16 + padded bias
__global__ void conv_wout(const float* __restrict__ W, __half* __restrict__ out,
                          const float* __restrict__ bin, float* __restrict__ bpad, int nq)
{
    int i = blockIdx.x * blockDim.x + threadIdx.x;
    if (i < NPADH) bpad[i] = (i < OUTD) ? bin[i] : 0.f;
    if (i >= nq) return;
    uint32_t* o = reinterpret_cast<uint32_t*>(out) + 2 * (size_t)i;
    size_t e = 4 * (size_t)i;
    if (e < (size_t)OUTD * H_) cast_quad(W + e, o);
    else { o[0] = 0; o[1] = 0; }
}

// ---------------- fp16 HMMA GEMM ----------------------------------------------
// C[M,Nout] = A2[M,K] @ B2[N,K]^T + bias.  M%128==0, N%256==0, K%64==0.
// mode bits: 1 = write fp32 C (cols < Nout), 2 = write fp16 C2, 4 = relu
#define NSTG  4
#define STGB  49152                 // A 16KB + B 32KB
#define GSMEM (NSTG * STGB)         // 196608

__global__ __launch_bounds__(512, 1)
void gemm_fp16(const __half* __restrict__ A2, const __half* __restrict__ B2,
               const float* __restrict__ bias, float* __restrict__ C,
               __half* __restrict__ C2,
               int M, int N, int K, int Nout, int mode)
{
    extern __shared__ char smem[];
    const uint32_t sb = smem_to_u32(smem);
    const int tid  = threadIdx.x;
    const int wid  = tid >> 5;
    const int lane = tid & 31;
    const int warp_m = wid >> 2;        // 0..3 -> 32-row block
    const int warp_n = wid & 3;         // 0..3 -> 64-col block
    const int tile_m = blockIdx.y * 128;
    const int tile_n = blockIdx.x * 256;
    const int NC = K >> 6;

    const int ra = tid >> 3;            // 0..63
    const int ca = tid & 7;
    const __half* gA = A2 + (size_t)(tile_m + ra) * K + ca * 8;
    const __half* gB = B2 + (size_t)(tile_n + ra) * K + ca * 8;
    const uint32_t dA = (uint32_t)(ra * 128 + ((ca ^ (ra & 7)) << 4));

    float acc[2][8][4];
#pragma unroll
    for (int i = 0; i < 2; i++)
#pragma unroll
        for (int j = 0; j < 8; j++)
#pragma unroll
            for (int k = 0; k < 4; k++) acc[i][j][k] = 0.f;

    auto issue = [&](int stage, int chunk) {
        uint32_t s = sb + stage * STGB;
        size_t ko = (size_t)chunk * 64;
        cp_async16(s + dA,        gA + ko);
        cp_async16(s + dA + 8192, gA + ko + (size_t)64 * K);
#pragma unroll
        for (int i = 0; i < 4; i++)
            cp_async16(s + 16384 + i * 8192 + dA, gB + ko + (size_t)(64 * i) * K);
        cp_commit();
    };

    issue(0, 0);
    if (1 < NC) issue(1, 1); else cp_commit();
    if (2 < NC) issue(2, 2); else cp_commit();

    const int l16 = lane & 15;
    const int g   = lane >> 3;

    for (int c = 0; c < NC; c++) {
        cp_wait2();
        __syncthreads();
        if (c + 3 < NC) issue((c + 3) & 3, c + 3); else cp_commit();

        uint32_t sA = sb + (c & 3) * STGB;
        uint32_t sB = sA + 16384;
#pragma unroll
        for (int ks = 0; ks < 4; ks++) {
            uint32_t a[2][4];
#pragma unroll
            for (int mt = 0; mt < 2; mt++) {
                int r = warp_m * 32 + mt * 16 + l16;
                uint32_t ku = (uint32_t)((ks * 2 + (lane >> 4)) ^ (r & 7));
                ldmx4(a[mt], sA + (uint32_t)r * 128 + (ku << 4));
            }
            uint32_t b[4][4];
#pragma unroll
            for (int p = 0; p < 4; p++) {
                int rn = warp_n * 64 + p * 16 + (g >> 1) * 8 + (lane & 7);
                uint32_t ku = (uint32_t)((ks * 2 + (g & 1)) ^ (rn & 7));
                ldmx4(b[p], sB + (uint32_t)rn * 128 + (ku << 4));
            }
#pragma unroll
            for (int mt = 0; mt < 2; mt++)
#pragma unroll
                for (int p = 0; p < 4; p++) {
                    mma16816(acc[mt][2 * p],     a[mt], b[p][0], b[p][1]);
                    mma16816(acc[mt][2 * p + 1], a[mt], b[p][2], b[p][3]);
                }
        }
        __syncthreads();
    }

    // epilogue
    const int r0    = lane >> 2;
    const int cpair = (lane & 3) * 2;
#pragma unroll
    for (int mt = 0; mt < 2; mt++) {
#pragma unroll
        for (int nt = 0; nt < 8; nt++) {
            int n  = tile_n + warp_n * 64 + nt * 8 + cpair;
            int m0 = tile_m + warp_m * 32 + mt * 16 + r0;
            if (n >= Nout) continue;
            float2 bv = *(const float2*)(bias + n);
            float v[2][2];
            v[0][0] = acc[mt][nt][0] + bv.x; v[0][1] = acc[mt][nt][1] + bv.y;
            v[1][0] = acc[mt][nt][2] + bv.x; v[1][1] = acc[mt][nt][3] + bv.y;
            if (mode & 4) {
#pragma unroll
                for (int i = 0; i < 2; i++) {
                    v[i][0] = fmaxf(v[i][0], 0.f); v[i][1] = fmaxf(v[i][1], 0.f);
                }
            }
            if (mode & 1) {
                *(float2*)(C + (size_t)m0 * Nout + n)       = make_float2(v[0][0], v[0][1]);
                *(float2*)(C + (size_t)(m0 + 8) * Nout + n) = make_float2(v[1][0], v[1][1]);
            }
            if (mode & 2) {
#pragma unroll
                for (int i = 0; i < 2; i++) {
                    int m = m0 + i * 8;
                    *(reinterpret_cast<uint32_t*>(C2) + (((size_t)m * Nout + n) >> 1)) =
                        pack_h2(__float2half(v[i][0]), __float2half(v[i][1]));
                }
            }
        }
    }
}

// ---------------- banded attention (writes fp16 ctx directly) ------------------
__global__ __launch_bounds__(256)
void attn_kernel(const float* __restrict__ qkv, __half* __restrict__ ctx2)
{
    int w    = (blockIdx.x * blockDim.x + threadIdx.x) >> 5;
    int lane = threadIdx.x & 31;
    if (w >= TOK * NHEAD) return;
    int t = w >> 2;
    int h = w & 3;
    int s = t / B_;
    int b = t - s * B_;

    const float* qp = qkv + (size_t)t * (3 * H_) + h * DH + lane * 8;
    float4 q0 = *(const float4*)(qp);
    float4 q1 = *(const float4*)(qp + 4);

    int lo  = s - WIN; if (lo < 0) lo = 0;
    int cnt = s - lo + 1;

    float sc[WIN + 1];
#pragma unroll
    for (int j = 0; j <= WIN; j++) {
        sc[j] = -1e30f;
        if (j < cnt) {
            int tj = (lo + j) * B_ + b;
            const float* kp = qkv + (size_t)tj * (3 * H_) + H_ + h * DH + lane * 8;
            float4 k0 = *(const float4*)(kp);
            float4 k1 = *(const float4*)(kp + 4);
            float p = q0.x * k0.x + q0.y * k0.y + q0.z * k0.z + q0.w * k0.w
                    + q1.x * k1.x + q1.y * k1.y + q1.z * k1.z + q1.w * k1.w;
#pragma unroll
            for (int o = 16; o; o >>= 1) p += __shfl_xor_sync(0xFFFFFFFFu, p, o);
            sc[j] = p * 0.0625f;
        }
    }
    float m = sc[0];
#pragma unroll
    for (int j = 1; j <= WIN; j++) m = fmaxf(m, sc[j]);
    float e[WIN + 1];
    float se = 0.f;
#pragma unroll
    for (int j = 0; j <= WIN; j++) {
        e[j] = (j < cnt) ? __expf(sc[j] - m) : 0.f;
        se += e[j];
    }
    float inv = 1.f / se;

    float cx[8];
#pragma unroll
    for (int i = 0; i < 8; i++) cx[i] = 0.f;
    for (int j = 0; j < cnt; j++) {
        int tj = (lo + j) * B_ + b;
        const float* vp = qkv + (size_t)tj * (3 * H_) + 2 * H_ + h * DH + lane * 8;
        float4 v0 = *(const float4*)(vp);
        float4 v1 = *(const float4*)(vp + 4);
        float a = e[j] * inv;
        cx[0] = fmaf(a, v0.x, cx[0]); cx[1] = fmaf(a, v0.y, cx[1]);
        cx[2] = fmaf(a, v0.z, cx[2]); cx[3] = fmaf(a, v0.w, cx[3]);
        cx[4] = fmaf(a, v1.x, cx[4]); cx[5] = fmaf(a, v1.y, cx[5]);
        cx[6] = fmaf(a, v1.z, cx[6]); cx[7] = fmaf(a, v1.w, cx[7]);
    }

    size_t e0 = (size_t)t * H_ + h * DH + lane * 8;
    uint32_t wbuf[4];
#pragma unroll
    for (int p = 0; p < 4; p++)
        wbuf[p] = pack_h2(__float2half(cx[2 * p]), __float2half(cx[2 * p + 1]));
    *(uint4*)(reinterpret_cast<uint32_t*>(ctx2) + (e0 >> 1)) = *(uint4*)wbuf;
}

// ---------------- residual + LayerNorm (dual write: fp32 + fp16) --------------
__device__ __forceinline__ float block_sum(float v, float* red)
{
#pragma unroll
    for (int o = 16; o; o >>= 1) v += __shfl_xor_sync(0xFFFFFFFFu, v, o);
    int wid = threadIdx.x >> 5, lane = threadIdx.x & 31;
    if (lane == 0) red[wid] = v;
    __syncthreads();
    if (threadIdx.x < 32) {
        float r = (threadIdx.x < 8) ? red[threadIdx.x] : 0.f;
#pragma unroll
        for (int o = 4; o; o >>= 1) r += __shfl_xor_sync(0xFFFFFFFFu, r, o);
        if (threadIdx.x == 0) red[0] = r;
    }
    __syncthreads();
    float r = red[0];
    __syncthreads();
    return r;
}

__global__ __launch_bounds__(256)
void resid_ln_kernel(float* __restrict__ x, const float* __restrict__ delta,
                     const float* __restrict__ scale, const float* __restrict__ bias,
                     __half* __restrict__ x2)
{
    __shared__ float red[8];
    int t   = blockIdx.x;
    int tid = threadIdx.x;
    size_t base = (size_t)t * H_ + tid * 4;

    float4 v = *(const float4*)(x + base);
    float4 d = *(const float4*)(delta + base);
    v.x += d.x; v.y += d.y; v.z += d.z; v.w += d.w;

    float s = v.x + v.y + v.z + v.w;
    float mean = block_sum(s, red) * (1.0f / H_);

    float dx = v.x - mean, dy = v.y - mean, dz = v.z - mean, dw = v.w - mean;
    float sq = dx * dx + dy * dy + dz * dz + dw * dw;
    float var = block_sum(sq, red) * (1.0f / H_);
    float rstd = rsqrtf(var + EPS);

    float4 sc = *(const float4*)(scale + tid * 4);
    float4 bi = *(const float4*)(bias + tid * 4);
    float4 o;
    o.x = dx * rstd * sc.x + bi.x;
    o.y = dy * rstd * sc.y + bi.y;
    o.z = dz * rstd * sc.z + bi.z;
    o.w = dw * rstd * sc.w + bi.w;
    *(float4*)(x + base) = o;

    uint32_t wbuf[2];
    wbuf[0] = pack_h2(__float2half(o.x), __float2half(o.y));
    wbuf[1] = pack_h2(__float2half(o.z), __float2half(o.w));
    *(uint2*)(reinterpret_cast<uint32_t*>(x2) + (base >> 1)) = *(uint2*)wbuf;
}

// ---------------- host orchestration ------------------------------------------
static inline void run_gemm(const __half* A2, const __half* B2,
                            const float* bias, float* C, __half* C2,
                            int M, int N, int K, int Nout, int mode)
{
    static int attr_set = 0;
    if (!attr_set) {
        cudaFuncSetAttribute(gemm_fp16, cudaFuncAttributeMaxDynamicSharedMemorySize, GSMEM);
        attr_set = 1;
    }
    dim3 grid(N / 256, M / 128);
    gemm_fp16<<<grid, 512, GSMEM>>>(A2, B2, bias, C, C2, M, N, K, Nout, mode);
}

extern "C" void kernel_launch(void* const* d_in, const int* in_sizes, int n_in,
                              void* d_out, int out_size)
{
    const float* src   = (const float*)d_in[0];
    const float* Wenc  = (const float*)d_in[1];
    const float* benc  = (const float*)d_in[2];
    const float* Wqkv  = (const float*)d_in[3];
    const float* bqkv  = (const float*)d_in[4];
    const float* Wo    = (const float*)d_in[5];
    const float* bo    = (const float*)d_in[6];
    const float* W1    = (const float*)d_in[7];
    const float* b1    = (const float*)d_in[8];
    const float* W2    = (const float*)d_in[9];
    const float* b2    = (const float*)d_in[10];
    const float* ln1_s = (const float*)d_in[11];
    const float* ln1_b = (const float*)d_in[12];
    const float* ln2_s = (const float*)d_in[13];
    const float* ln2_b = (const float*)d_in[14];
    const float* Wout  = (const float*)d_in[15];
    const float* bout  = (const float*)d_in[16];
    float* out = (float*)d_out;

    float *x, *qkv, *tmp, *bout_pad;
    __half *src2, *x2, *ctx2, *h12, *wenc2, *wqkv2, *wo2, *w12, *w22, *wout2;
    cudaGetSymbolAddress((void**)&x,    g_x);
    cudaGetSymbolAddress((void**)&qkv,  g_qkv);
    cudaGetSymbolAddress((void**)&tmp,  g_tmp);
    cudaGetSymbolAddress((void**)&bout_pad, g_bout_pad);
    cudaGetSymbolAddress((void**)&src2, g_src2);
    cudaGetSymbolAddress((void**)&x2,   g_x2);
    cudaGetSymbolAddress((void**)&ctx2, g_ctx2);
    cudaGetSymbolAddress((void**)&h12,  g_h12);
    cudaGetSymbolAddress((void**)&wenc2, g_wenc2);
    cudaGetSymbolAddress((void**)&wqkv2, g_wqkv2);
    cudaGetSymbolAddress((void**)&wo2,   g_wo2);
    cudaGetSymbolAddress((void**)&w12,   g_w12);
    cudaGetSymbolAddress((void**)&w22,   g_w22);
    cudaGetSymbolAddress((void**)&wout2, g_wout2);

    // launch 0: src + Wenc cast
    {
        int nqA = TOK * INDIM / 4, nqB = H_ * INDIM / 4;
        int nqT = nqA + nqB;
        conv_seg2<<<(nqT + 255) / 256, 256>>>(src, Wenc, src2, wenc2, nqA, nqT);
    }
    // launch 1: Wqkv cast
    {
        int nq = (int)((size_t)L_ * 3 * H_ * H_ / 4);
        conv_cast<<<(nq + 255) / 256, 256>>>(Wqkv, wqkv2, nq);
    }
    // launch 2: Wo/W1/W2 cast
    {
        int nq = (int)((size_t)L_ * H_ * H_ / 4);
        dim3 grid((nq + 255) / 256, 3);
        conv_cast3<<<grid, 256>>>(Wo, W1, W2, wo2, w12, w22, nq);
    }
    // launch 3: Wout pad-cast + bias pad
    {
        int nq = NPADH * H_ / 4;
        conv_wout<<<(nq + 255) / 256, 256>>>(Wout, wout2, bout, bout_pad, nq);
    }
    // launch 4: encoder GEMM (x + x2)
    run_gemm(src2, wenc2, benc, x, x2, TOK, H_, INDIM, H_, 1 | 2);

    for (int l = 0; l < L_; l++) {
        const __half* wqkv2_l = wqkv2 + (size_t)l * 3 * H_ * H_;
        const __half* wo2_l   = wo2   + (size_t)l * H_ * H_;
        const __half* w12_l   = w12   + (size_t)l * DFF_ * H_;
        const __half* w22_l   = w22   + (size_t)l * H_ * DFF_;
        const float* bqkv_l = bqkv + (size_t)l * 3 * H_;
        const float* bo_l   = bo   + (size_t)l * H_;
        const float* b1_l   = b1   + (size_t)l * DFF_;
        const float* b2_l   = b2   + (size_t)l * H_;

        // launch 5 (layer 0): QKV GEMM -> ncu -s 5 profiles this
        run_gemm(x2, wqkv2_l, bqkv_l, qkv, nullptr, TOK, 3 * H_, H_, 3 * H_, 1);
        attn_kernel<<<(TOK * NHEAD) / 8, 256>>>(qkv, ctx2);
        run_gemm(ctx2, wo2_l, bo_l, tmp, nullptr, TOK, H_, H_, H_, 1);
        resid_ln_kernel<<<TOK, 256>>>(x, tmp, ln1_s + (size_t)l * H_, ln1_b + (size_t)l * H_, x2);
        run_gemm(x2, w12_l, b1_l, nullptr, h12, TOK, DFF_, H_, DFF_, 2 | 4);
        run_gemm(h12, w22_l, b2_l, tmp, nullptr, TOK, H_, DFF_, H_, 1);
        resid_ln_kernel<<<TOK, 256>>>(x, tmp, ln2_s + (size_t)l * H_, ln2_b + (size_t)l * H_, x2);
    }

    // out = x @ Wout^T + bout  (padded N=256, masked store to 64)
    run_gemm(x2, wout2, bout_pad, out, nullptr, TOK, NPADH, H_, OUTD, 1);
}

// round 14
// speedup vs baseline: 6.4999x; 1.0038x over previous
#include <cuda_runtime.h>
#include <cuda_fp16.h>
#include <cstdint>
#include <cstddef>

#define S_    2048
#define B_    4
#define INDIM 64
#define H_    1024
#define DFF_  1024
#define OUTD  64
#define L_    3
#define NHEAD 4
#define DH    (H_ / NHEAD)   // 256
#define WIN   4
#define TOK   (S_ * B_)      // 8192
#define EPS   1e-5f
#define NPADH 256            // padded head N

// ---------------- scratch (static device globals) -----------------------------
__device__ float g_x[TOK * H_];
__device__ float g_tmp[TOK * H_];
__device__ float g_bout_pad[NPADH];

__device__ __align__(256) __half g_qkv2[TOK * 3 * H_];
__device__ __align__(256) __half g_src2[TOK * INDIM];
__device__ __align__(256) __half g_x2[TOK * H_];
__device__ __align__(256) __half g_ctx2[TOK * H_];
__device__ __align__(256) __half g_h12[TOK * H_];
__device__ __align__(256) __half g_wenc2[H_ * INDIM];
__device__ __align__(256) __half g_wqkv2[L_ * 3 * H_ * H_];
__device__ __align__(256) __half g_wo2[L_ * H_ * H_];
__device__ __align__(256) __half g_w12[L_ * DFF_ * H_];
__device__ __align__(256) __half g_w22[L_ * H_ * DFF_];
__device__ __align__(256) __half g_wout2[NPADH * H_];

// ---------------- helpers -----------------------------------------------------
__device__ __forceinline__ uint32_t smem_to_u32(const void* p) {
    uint32_t a;
    asm("{ .reg .u64 t; cvta.to.shared.u64 t, %1; cvt.u32.u64 %0, t; }"
        : "=r"(a) : "l"(p));
    return a;
}
__device__ __forceinline__ uint32_t pack_h2(__half a, __half b) {
    __half2 t = __halves2half2(a, b);
    return *reinterpret_cast<uint32_t*>(&t);
}
__device__ __forceinline__ void cp_async16(uint32_t dst, const void* src) {
    asm volatile("cp.async.cg.shared.global [%0], [%1], 16;"
                 :: "r"(dst), "l"(src) : "memory");
}
__device__ __forceinline__ void cp_commit() {
    asm volatile("cp.async.commit_group;" ::: "memory");
}
__device__ __forceinline__ void cp_wait2() {
    asm volatile("cp.async.wait_group 2;" ::: "memory");
}
__device__ __forceinline__ void ldmx4(uint32_t* r, uint32_t a) {
    asm volatile("ldmatrix.sync.aligned.m8n8.x4.shared.b16 {%0,%1,%2,%3}, [%4];"
                 : "=r"(r[0]), "=r"(r[1]), "=r"(r[2]), "=r"(r[3]) : "r"(a));
}
__device__ __forceinline__ void mma16816(float* d, const uint32_t* a,
                                         uint32_t b0, uint32_t b1) {
    asm volatile("mma.sync.aligned.m16n8k16.row.col.f32.f16.f16.f32 "
                 "{%0,%1,%2,%3}, {%4,%5,%6,%7}, {%8,%9}, {%0,%1,%2,%3};"
                 : "+f"(d[0]), "+f"(d[1]), "+f"(d[2]), "+f"(d[3])
                 : "r"(a[0]), "r"(a[1]), "r"(a[2]), "r"(a[3]), "r"(b0), "r"(b1));
}
// load 8 consecutive halves -> 8 floats
__device__ __forceinline__ void load8h(const __half* p, float* f) {
    uint4 u = *(const uint4*)p;
    const uint32_t w[4] = { u.x, u.y, u.z, u.w };
#pragma unroll
    for (int i = 0; i < 4; i++) {
        __half2 h2 = *reinterpret_cast<const __half2*>(&w[i]);
        float2 f2 = __half22float2(h2);
        f[2 * i] = f2.x; f[2 * i + 1] = f2.y;
    }
}

// ---------------- conversion: fp32 -> fp16 (quad per thread) -------------------
__device__ __forceinline__ void cast_quad(const float* in, uint32_t* o) {
    float4 v = *(const float4*)in;
    o[0] = pack_h2(__float2half(v.x), __float2half(v.y));
    o[1] = pack_h2(__float2half(v.z), __float2half(v.w));
}

__global__ void conv_seg2(const float* __restrict__ a, const float* __restrict__ b,
                          __half* __restrict__ oa, __half* __restrict__ ob, int nqA, int nqTot)
{
    int i = blockIdx.x * blockDim.x + threadIdx.x;
    if (i >= nqTot) return;
    if (i < nqA) cast_quad(a + 4 * (size_t)i, reinterpret_cast<uint32_t*>(oa) + 2 * (size_t)i);
    else {
        int j = i - nqA;
        cast_quad(b + 4 * (size_t)j, reinterpret_cast<uint32_t*>(ob) + 2 * (size_t)j);
    }
}

__global__ void conv_cast(const float* __restrict__ in, __half* __restrict__ out, int nq)
{
    int i = blockIdx.x * blockDim.x + threadIdx.x;
    if (i >= nq) return;
    cast_quad(in + 4 * (size_t)i, reinterpret_cast<uint32_t*>(out) + 2 * (size_t)i);
}

__global__ void conv_cast3(const float* __restrict__ a, const float* __restrict__ b,
                           const float* __restrict__ c,
                           __half* __restrict__ oa, __half* __restrict__ ob,
                           __half* __restrict__ oc, int nq)
{
    int i = blockIdx.x * blockDim.x + threadIdx.x;
    if (i >= nq) return;
    const float* in = (blockIdx.y == 0) ? a : (blockIdx.y == 1) ? b : c;
    __half* out = (blockIdx.y == 0) ? oa : (blockIdx.y == 1) ? ob : oc;
    cast_quad(in + 4 * (size_t)i, reinterpret_cast<uint32_t*>(out) + 2 * (size_t)i);
}

__global__ void conv_wout(const float* __restrict__ W, __half* __restrict__ out,
                          const float* __restrict__ bin, float* __restrict__ bpad, int nq)
{
    int i = blockIdx.x * blockDim.x + threadIdx.x;
    if (i < NPADH) bpad[i] = (i < OUTD) ? bin[i] : 0.f;
    if (i >= nq) return;
    uint32_t* o = reinterpret_cast<uint32_t*>(out) + 2 * (size_t)i;
    size_t e = 4 * (size_t)i;
    if (e < (size_t)OUTD * H_) cast_quad(W + e, o);
    else { o[0] = 0; o[1] = 0; }
}

// ---------------- fp16 HMMA GEMM (256 thr, 128x256 CTA, 64x64 warp) -----------
// C[M,Nout] = A2[M,K] @ B2[N,K]^T + bias.  M%128==0, N%256==0, K%64==0.
// mode bits: 1 = write fp32 C (cols < Nout), 2 = write fp16 C2, 4 = relu
#define NSTG  4
#define STGB  49152                 // A 16KB + B 32KB
#define GSMEM (NSTG * STGB)         // 196608

__global__ __launch_bounds__(256, 1)
void gemm_fp16(const __half* __restrict__ A2, const __half* __restrict__ B2,
               const float* __restrict__ bias, float* __restrict__ C,
               __half* __restrict__ C2,
               int M, int N, int K, int Nout, int mode)
{
    extern __shared__ char smem[];
    const uint32_t sb = smem_to_u32(smem);
    const int tid  = threadIdx.x;
    const int wid  = tid >> 5;
    const int lane = tid & 31;
    const int warp_m = wid >> 2;        // 0..1 -> 64-row block
    const int warp_n = wid & 3;         // 0..3 -> 64-col block
    const int tile_m = blockIdx.y * 128;
    const int tile_n = blockIdx.x * 256;
    const int NC = K >> 6;

    const int ra = tid >> 3;            // 0..31
    const int ca = tid & 7;
    const __half* gA = A2 + (size_t)(tile_m + ra) * K + ca * 8;
    const __half* gB = B2 + (size_t)(tile_n + ra) * K + ca * 8;
    const uint32_t dA = (uint32_t)(ra * 128 + ((ca ^ (ra & 7)) << 4));

    float acc[4][8][4];
#pragma unroll
    for (int i = 0; i < 4; i++)
#pragma unroll
        for (int j = 0; j < 8; j++)
#pragma unroll
            for (int k = 0; k < 4; k++) acc[i][j][k] = 0.f;

    auto issue = [&](int stage, int chunk) {
        uint32_t s = sb + stage * STGB;
        size_t ko = (size_t)chunk * 64;
#pragma unroll
        for (int i = 0; i < 4; i++)
            cp_async16(s + dA + i * 4096, gA + ko + (size_t)(32 * i) * K);
#pragma unroll
        for (int i = 0; i < 8; i++)
            cp_async16(s + 16384 + dA + i * 4096, gB + ko + (size_t)(32 * i) * K);
        cp_commit();
    };

    issue(0, 0);
    if (1 < NC) issue(1, 1); else cp_commit();
    if (2 < NC) issue(2, 2); else cp_commit();

    const int l16 = lane & 15;
    const int g   = lane >> 3;

    for (int c = 0; c < NC; c++) {
        cp_wait2();
        __syncthreads();
        if (c + 3 < NC) issue((c + 3) & 3, c + 3); else cp_commit();

        uint32_t sA = sb + (c & 3) * STGB;
        uint32_t sB = sA + 16384;
#pragma unroll
        for (int ks = 0; ks < 4; ks++) {
            uint32_t a[4][4];
#pragma unroll
            for (int mt = 0; mt < 4; mt++) {
                int r = warp_m * 64 + mt * 16 + l16;
                uint32_t ku = (uint32_t)((ks * 2 + (lane >> 4)) ^ (r & 7));
                ldmx4(a[mt], sA + (uint32_t)r * 128 + (ku << 4));
            }
            uint32_t b[4][4];
#pragma unroll
            for (int p = 0; p < 4; p++) {
                int rn = warp_n * 64 + p * 16 + (g >> 1) * 8 + (lane & 7);
                uint32_t ku = (uint32_t)((ks * 2 + (g & 1)) ^ (rn & 7));
                ldmx4(b[p], sB + (uint32_t)rn * 128 + (ku << 4));
            }
#pragma unroll
            for (int mt = 0; mt < 4; mt++)
#pragma unroll
                for (int p = 0; p < 4; p++) {
                    mma16816(acc[mt][2 * p],     a[mt], b[p][0], b[p][1]);
                    mma16816(acc[mt][2 * p + 1], a[mt], b[p][2], b[p][3]);
                }
        }
        // no bottom sync: next iteration's top sync orders stage reuse
    }

    // epilogue
    const int r0    = lane >> 2;
    const int cpair = (lane & 3) * 2;
#pragma unroll
    for (int mt = 0; mt < 4; mt++) {
#pragma unroll
        for (int nt = 0; nt < 8; nt++) {
            int n  = tile_n + warp_n * 64 + nt * 8 + cpair;
            int m0 = tile_m + warp_m * 64 + mt * 16 + r0;
            if (n >= Nout) continue;
            float2 bv = *(const float2*)(bias + n);
            float v[2][2];
            v[0][0] = acc[mt][nt][0] + bv.x; v[0][1] = acc[mt][nt][1] + bv.y;
            v[1][0] = acc[mt][nt][2] + bv.x; v[1][1] = acc[mt][nt][3] + bv.y;
            if (mode & 4) {
#pragma unroll
                for (int i = 0; i < 2; i++) {
                    v[i][0] = fmaxf(v[i][0], 0.f); v[i][1] = fmaxf(v[i][1], 0.f);
                }
            }
            if (mode & 1) {
                *(float2*)(C + (size_t)m0 * Nout + n)       = make_float2(v[0][0], v[0][1]);
                *(float2*)(C + (size_t)(m0 + 8) * Nout + n) = make_float2(v[1][0], v[1][1]);
            }
            if (mode & 2) {
#pragma unroll
                for (int i = 0; i < 2; i++) {
                    int m = m0 + i * 8;
                    *(reinterpret_cast<uint32_t*>(C2) + (((size_t)m * Nout + n) >> 1)) =
                        pack_h2(__float2half(v[i][0]), __float2half(v[i][1]));
                }
            }
        }
    }
}

// ---------------- banded attention (fp16 qkv in, fp16 ctx out) -----------------
__global__ __launch_bounds__(256)
void attn_kernel(const __half* __restrict__ qkv, __half* __restrict__ ctx2)
{
    int w    = (blockIdx.x * blockDim.x + threadIdx.x) >> 5;
    int lane = threadIdx.x & 31;
    if (w >= TOK * NHEAD) return;
    int t = w >> 2;
    int h = w & 3;
    int s = t / B_;
    int b = t - s * B_;

    float q[8];
    load8h(qkv + (size_t)t * (3 * H_) + h * DH + lane * 8, q);

    int lo  = s - WIN; if (lo < 0) lo = 0;
    int cnt = s - lo + 1;

    float sc[WIN + 1];
#pragma unroll
    for (int j = 0; j <= WIN; j++) {
        sc[j] = -1e30f;
        if (j < cnt) {
            int tj = (lo + j) * B_ + b;
            float k[8];
            load8h(qkv + (size_t)tj * (3 * H_) + H_ + h * DH + lane * 8, k);
            float p = 0.f;
#pragma unroll
            for (int i = 0; i < 8; i++) p = fmaf(q[i], k[i], p);
#pragma unroll
            for (int o = 16; o; o >>= 1) p += __shfl_xor_sync(0xFFFFFFFFu, p, o);
            sc[j] = p * 0.0625f;
        }
    }
    float m = sc[0];
#pragma unroll
    for (int j = 1; j <= WIN; j++) m = fmaxf(m, sc[j]);
    float e[WIN + 1];
    float se = 0.f;
#pragma unroll
    for (int j = 0; j <= WIN; j++) {
        e[j] = (j < cnt) ? __expf(sc[j] - m) : 0.f;
        se += e[j];
    }
    float inv = 1.f / se;

    float cx[8];
#pragma unroll
    for (int i = 0; i < 8; i++) cx[i] = 0.f;
    for (int j = 0; j < cnt; j++) {
        int tj = (lo + j) * B_ + b;
        float vv[8];
        load8h(qkv + (size_t)tj * (3 * H_) + 2 * H_ + h * DH + lane * 8, vv);
        float a = e[j] * inv;
#pragma unroll
        for (int i = 0; i < 8; i++) cx[i] = fmaf(a, vv[i], cx[i]);
    }

    size_t e0 = (size_t)t * H_ + h * DH + lane * 8;
    uint32_t wbuf[4];
#pragma unroll
    for (int p = 0; p < 4; p++)
        wbuf[p] = pack_h2(__float2half(cx[2 * p]), __float2half(cx[2 * p + 1]));
    *(uint4*)(reinterpret_cast<uint32_t*>(ctx2) + (e0 >> 1)) = *(uint4*)wbuf;
}

// ---------------- residual + LayerNorm (dual write: fp32 + fp16) --------------
__device__ __forceinline__ float block_sum(float v, float* red)
{
#pragma unroll
    for (int o = 16; o; o >>= 1) v += __shfl_xor_sync(0xFFFFFFFFu, v, o);
    int wid = threadIdx.x >> 5, lane = threadIdx.x & 31;
    if (lane == 0) red[wid] = v;
    __syncthreads();
    if (threadIdx.x < 32) {
        float r = (threadIdx.x < 8) ? red[threadIdx.x] : 0.f;
#pragma unroll
        for (int o = 4; o; o >>= 1) r += __shfl_xor_sync(0xFFFFFFFFu, r, o);
        if (threadIdx.x == 0) red[0] = r;
    }
    __syncthreads();
    float r = red[0];
    __syncthreads();
    return r;
}

__global__ __launch_bounds__(256)
void resid_ln_kernel(float* __restrict__ x, const float* __restrict__ delta,
                     const float* __restrict__ scale, const float* __restrict__ bias,
                     __half* __restrict__ x2)
{
    __shared__ float red[8];
    int t   = blockIdx.x;
    int tid = threadIdx.x;
    size_t base = (size_t)t * H_ + tid * 4;

    float4 v = *(const float4*)(x + base);
    float4 d = *(const float4*)(delta + base);
    v.x += d.x; v.y += d.y; v.z += d.z; v.w += d.w;

    float s = v.x + v.y + v.z + v.w;
    float mean = block_sum(s, red) * (1.0f / H_);

    float dx = v.x - mean, dy = v.y - mean, dz = v.z - mean, dw = v.w - mean;
    float sq = dx * dx + dy * dy + dz * dz + dw * dw;
    float var = block_sum(sq, red) * (1.0f / H_);
    float rstd = rsqrtf(var + EPS);

    float4 sc = *(const float4*)(scale + tid * 4);
    float4 bi = *(const float4*)(bias + tid * 4);
    float4 o;
    o.x = dx * rstd * sc.x + bi.x;
    o.y = dy * rstd * sc.y + bi.y;
    o.z = dz * rstd * sc.z + bi.z;
    o.w = dw * rstd * sc.w + bi.w;
    *(float4*)(x + base) = o;

    uint32_t wbuf[2];
    wbuf[0] = pack_h2(__float2half(o.x), __float2half(o.y));
    wbuf[1] = pack_h2(__float2half(o.z), __float2half(o.w));
    *(uint2*)(reinterpret_cast<uint32_t*>(x2) + (base >> 1)) = *(uint2*)wbuf;
}

// ---------------- host orchestration ------------------------------------------
static inline void run_gemm(const __half* A2, const __half* B2,
                            const float* bias, float* C, __half* C2,
                            int M, int N, int K, int Nout, int mode)
{
    static int attr_set = 0;
    if (!attr_set) {
        cudaFuncSetAttribute(gemm_fp16, cudaFuncAttributeMaxDynamicSharedMemorySize, GSMEM);
        attr_set = 1;
    }
    dim3 grid(N / 256, M / 128);
    gemm_fp16<<<grid, 256, GSMEM>>>(A2, B2, bias, C, C2, M, N, K, Nout, mode);
}

extern "C" void kernel_launch(void* const* d_in, const int* in_sizes, int n_in,
                              void* d_out, int out_size)
{
    const float* src   = (const float*)d_in[0];
    const float* Wenc  = (const float*)d_in[1];
    const float* benc  = (const float*)d_in[2];
    const float* Wqkv  = (const float*)d_in[3];
    const float* bqkv  = (const float*)d_in[4];
    const float* Wo    = (const float*)d_in[5];
    const float* bo    = (const float*)d_in[6];
    const float* W1    = (const float*)d_in[7];
    const float* b1    = (const float*)d_in[8];
    const float* W2    = (const float*)d_in[9];
    const float* b2    = (const float*)d_in[10];
    const float* ln1_s = (const float*)d_in[11];
    const float* ln1_b = (const float*)d_in[12];
    const float* ln2_s = (const float*)d_in[13];
    const float* ln2_b = (const float*)d_in[14];
    const float* Wout  = (const float*)d_in[15];
    const float* bout  = (const float*)d_in[16];
    float* out = (float*)d_out;

    float *x, *tmp, *bout_pad;
    __half *qkv2, *src2, *x2, *ctx2, *h12, *wenc2, *wqkv2, *wo2, *w12, *w22, *wout2;
    cudaGetSymbolAddress((void**)&x,    g_x);
    cudaGetSymbolAddress((void**)&tmp,  g_tmp);
    cudaGetSymbolAddress((void**)&bout_pad, g_bout_pad);
    cudaGetSymbolAddress((void**)&qkv2, g_qkv2);
    cudaGetSymbolAddress((void**)&src2, g_src2);
    cudaGetSymbolAddress((void**)&x2,   g_x2);
    cudaGetSymbolAddress((void**)&ctx2, g_ctx2);
    cudaGetSymbolAddress((void**)&h12,  g_h12);
    cudaGetSymbolAddress((void**)&wenc2, g_wenc2);
    cudaGetSymbolAddress((void**)&wqkv2, g_wqkv2);
    cudaGetSymbolAddress((void**)&wo2,   g_wo2);
    cudaGetSymbolAddress((void**)&w12,   g_w12);
    cudaGetSymbolAddress((void**)&w22,   g_w22);
    cudaGetSymbolAddress((void**)&wout2, g_wout2);

    // launch 0: src + Wenc cast
    {
        int nqA = TOK * INDIM / 4, nqB = H_ * INDIM / 4;
        int nqT = nqA + nqB;
        conv_seg2<<<(nqT + 255) / 256, 256>>>(src, Wenc, src2, wenc2, nqA, nqT);
    }
    // launch 1: Wqkv cast
    {
        int nq = (int)((size_t)L_ * 3 * H_ * H_ / 4);
        conv_cast<<<(nq + 255) / 256, 256>>>(Wqkv, wqkv2, nq);
    }
    // launch 2: Wo/W1/W2 cast
    {
        int nq = (int)((size_t)L_ * H_ * H_ / 4);
        dim3 grid((nq + 255) / 256, 3);
        conv_cast3<<<grid, 256>>>(Wo, W1, W2, wo2, w12, w22, nq);
    }
    // launch 3: Wout pad-cast + bias pad
    {
        int nq = NPADH * H_ / 4;
        conv_wout<<<(nq + 255) / 256, 256>>>(Wout, wout2, bout, bout_pad, nq);
    }
    // launch 4: encoder GEMM (x + x2)
    run_gemm(src2, wenc2, benc, x, x2, TOK, H_, INDIM, H_, 1 | 2);

    for (int l = 0; l < L_; l++) {
        const __half* wqkv2_l = wqkv2 + (size_t)l * 3 * H_ * H_;
        const __half* wo2_l   = wo2   + (size_t)l * H_ * H_;
        const __half* w12_l   = w12   + (size_t)l * DFF_ * H_;
        const __half* w22_l   = w22   + (size_t)l * H_ * DFF_;
        const float* bqkv_l = bqkv + (size_t)l * 3 * H_;
        const float* bo_l   = bo   + (size_t)l * H_;
        const float* b1_l   = b1   + (size_t)l * DFF_;
        const float* b2_l   = b2   + (size_t)l * H_;

        // launch 5 (layer 0): QKV GEMM (fp16 out) -> ncu -s 5 profiles this
        run_gemm(x2, wqkv2_l, bqkv_l, nullptr, qkv2, TOK, 3 * H_, H_, 3 * H_, 2);
        attn_kernel<<<(TOK * NHEAD) / 8, 256>>>(qkv2, ctx2);
        run_gemm(ctx2, wo2_l, bo_l, tmp, nullptr, TOK, H_, H_, H_, 1);
        resid_ln_kernel<<<TOK, 256>>>(x, tmp, ln1_s + (size_t)l * H_, ln1_b + (size_t)l * H_, x2);
        run_gemm(x2, w12_l, b1_l, nullptr, h12, TOK, DFF_, H_, DFF_, 2 | 4);
        run_gemm(h12, w22_l, b2_l, tmp, nullptr, TOK, H_, DFF_, H_, 1);
        resid_ln_kernel<<<TOK, 256>>>(x, tmp, ln2_s + (size_t)l * H_, ln2_b + (size_t)l * H_, x2);
    }

    // out = x @ Wout^T + bout  (padded N=256, masked store to 64)
    run_gemm(x2, wout2, bout_pad, out, nullptr, TOK, NPADH, H_, OUTD, 1);
}